// round 2
// baseline (speedup 1.0000x reference)
#include <cuda_runtime.h>
#include <cuda_fp16.h>
#include <cstdint>

#define N_DIM  2048
#define T_SEQ  8192
#define G_DIM  6144
#define NBLK   128     // persistent blocks (1 per SM, all resident)
#define NTHR   512
#define NWARP  16
#define PB     16      // output elements per block
#define NFRAG  6       // n-fragments of 8 cols (48 cols per block)
#define KFRAG  8       // k-fragments of 16 per warp (128 k per warp)

// ---- scratch (device globals: allocation-free rule) ----
__device__ __half        g_x16[(size_t)T_SEQ * N_DIM];          // 32 MB
__device__ __half        g_WxT16[(size_t)G_DIM * N_DIM];        // 25 MB (transposed: [n][k])
__device__ float         g_gx[(size_t)T_SEQ * G_DIM];           // 192 MB
__device__ unsigned int  g_whpack[NBLK * NWARP * NFRAG * KFRAG * 32 * 2]; // 25 MB packed B-frags
__device__ uint4         g_hbuf[2][NBLK][2];                    // h broadcast: 32B per block, double-buffered
__device__ unsigned int  g_flag[NBLK];                          // per-block step watermark

// ---------------- reset ----------------
__global__ void reset_k() {
    int t = threadIdx.x;
    if (t < NBLK) g_flag[t] = 0u;
    uint4 z = make_uint4(0u, 0u, 0u, 0u);
    for (int i = t; i < 2 * NBLK * 2; i += blockDim.x)
        ((uint4*)g_hbuf)[i] = z;
}

// ---------------- convert x -> fp16 ----------------
__global__ void conv_x(const float* __restrict__ x) {
    const float2* x2 = (const float2*)x;
    __half2* o = (__half2*)g_x16;
    size_t n = (size_t)T_SEQ * N_DIM / 2;
    for (size_t i = blockIdx.x * (size_t)blockDim.x + threadIdx.x; i < n;
         i += (size_t)gridDim.x * blockDim.x)
        o[i] = __float22half2_rn(x2[i]);
}

// ------------- convert+transpose Wx -> WxT fp16 [n][k] -------------
__global__ void conv_wxt(const float* __restrict__ Wx) {
    size_t idx = blockIdx.x * (size_t)blockDim.x + threadIdx.x; // over K*G
    if (idx >= (size_t)N_DIM * G_DIM) return;
    int k = (int)(idx / G_DIM);
    int j = (int)(idx % G_DIM);
    g_WxT16[(size_t)j * N_DIM + k] = __float2half(Wx[idx]);
}

// ------------- pack Wh into per-block mma B fragments (fp16) -------------
// pidx = ((((b*16 + w)*6 + nf)*8 + kf)*32 + lane)*2 + r
__global__ void pack_wh(const float* __restrict__ Wh) {
    int idx = blockIdx.x * blockDim.x + threadIdx.x;
    if (idx >= NBLK * NWARP * NFRAG * KFRAG * 32 * 2) return;
    int r    = idx & 1;
    int l    = (idx >> 1) & 31;
    int kf   = (idx >> 6) & 7;
    int rest = idx >> 9;           // (b*16 + w)*6 + nf
    int nf   = rest % 6;
    int bw   = rest / 6;
    int w    = bw & 15;
    int b    = bw >> 4;
    int tid  = l & 3, gid = l >> 2;
    int grp  = nf >> 1;                                  // 0:z 1:r 2:n
    int j    = grp * N_DIM + b * PB + (nf & 1) * 8 + gid; // global column
    int k    = w * 128 + kf * 16 + r * 8 + 2 * tid;       // global k
    __half2 h;
    h.x = __float2half(Wh[(size_t)k * G_DIM + j]);
    h.y = __float2half(Wh[(size_t)(k + 1) * G_DIM + j]);
    g_whpack[idx] = *(unsigned int*)&h;
}

// ---------------- gx = x @ Wx + b  (fp16 mma, fp32 accum) ----------------
__global__ void __launch_bounds__(256) gemm_gx(const float* __restrict__ bias) {
    __shared__ __half As[128 * 40];
    __shared__ __half Bs[128 * 40];
    const int m0 = blockIdx.y * 128, n0 = blockIdx.x * 128;
    const int t = threadIdx.x, w = t >> 5, l = t & 31, tid = l & 3, gid = l >> 2;
    const int wm = w & 3, wn = w >> 2;
    float acc[2][8][4];
#pragma unroll
    for (int mt = 0; mt < 2; ++mt)
#pragma unroll
        for (int nt = 0; nt < 8; ++nt)
#pragma unroll
            for (int q = 0; q < 4; ++q) acc[mt][nt][q] = 0.f;

    for (int kt = 0; kt < N_DIM; kt += 32) {
        {
            int r = t >> 2, c = (t & 3) * 8;
            *(uint4*)(As + r * 40 + c)        = *(const uint4*)(g_x16  + (size_t)(m0 + r)      * N_DIM + kt + c);
            *(uint4*)(As + (r + 64) * 40 + c) = *(const uint4*)(g_x16  + (size_t)(m0 + r + 64) * N_DIM + kt + c);
            *(uint4*)(Bs + r * 40 + c)        = *(const uint4*)(g_WxT16 + (size_t)(n0 + r)      * N_DIM + kt + c);
            *(uint4*)(Bs + (r + 64) * 40 + c) = *(const uint4*)(g_WxT16 + (size_t)(n0 + r + 64) * N_DIM + kt + c);
        }
        __syncthreads();
#pragma unroll
        for (int s = 0; s < 2; ++s) {
            const int ko = s * 16;
            unsigned a[2][4];
#pragma unroll
            for (int mt = 0; mt < 2; ++mt) {
                int rb = wm * 32 + mt * 16;
                a[mt][0] = *(const unsigned*)(As + (rb + gid)     * 40 + ko + 2 * tid);
                a[mt][1] = *(const unsigned*)(As + (rb + gid + 8) * 40 + ko + 2 * tid);
                a[mt][2] = *(const unsigned*)(As + (rb + gid)     * 40 + ko + 2 * tid + 8);
                a[mt][3] = *(const unsigned*)(As + (rb + gid + 8) * 40 + ko + 2 * tid + 8);
            }
#pragma unroll
            for (int nt = 0; nt < 8; ++nt) {
                int cb = wn * 64 + nt * 8 + gid;
                unsigned b0 = *(const unsigned*)(Bs + cb * 40 + ko + 2 * tid);
                unsigned b1 = *(const unsigned*)(Bs + cb * 40 + ko + 2 * tid + 8);
#pragma unroll
                for (int mt = 0; mt < 2; ++mt) {
                    asm volatile(
                        "mma.sync.aligned.m16n8k16.row.col.f32.f16.f16.f32 "
                        "{%0,%1,%2,%3},{%4,%5,%6,%7},{%8,%9},{%0,%1,%2,%3};"
                        : "+f"(acc[mt][nt][0]), "+f"(acc[mt][nt][1]),
                          "+f"(acc[mt][nt][2]), "+f"(acc[mt][nt][3])
                        : "r"(a[mt][0]), "r"(a[mt][1]), "r"(a[mt][2]), "r"(a[mt][3]),
                          "r"(b0), "r"(b1));
                }
            }
        }
        __syncthreads();
    }
#pragma unroll
    for (int mt = 0; mt < 2; ++mt)
#pragma unroll
        for (int nt = 0; nt < 8; ++nt) {
            int row = m0 + wm * 32 + mt * 16 + gid;
            int col = n0 + wn * 64 + nt * 8 + 2 * tid;
            float b0v = __ldg(bias + col), b1v = __ldg(bias + col + 1);
            g_gx[(size_t)row * G_DIM + col]           = acc[mt][nt][0] + b0v;
            g_gx[(size_t)row * G_DIM + col + 1]       = acc[mt][nt][1] + b1v;
            g_gx[(size_t)(row + 8) * G_DIM + col]     = acc[mt][nt][2] + b0v;
            g_gx[(size_t)(row + 8) * G_DIM + col + 1] = acc[mt][nt][3] + b1v;
        }
}

// ---------------- persistent GRU scan (dataflow sync, no grid barrier) ----------------
// dynamic smem layout (bytes):
//   [0,196608)        packed Wh fragments (49152 u32)
//   [196608,200704)   h16s: per-warp h slice, 16 warps x 64 u32 (256B each)
//   [200704,206848)   red[2][16][48] f32 (double-buffered partials)
//   [206848,206880)   hstage[16] u16 (staging for publish)
#define SMEM_SCAN 206912

__global__ void __launch_bounds__(NTHR, 1) gru_scan(float* __restrict__ out) {
    extern __shared__ unsigned char smem[];
    unsigned int* wp    = (unsigned int*)smem;
    unsigned int* h16sw = (unsigned int*)(smem + 196608) + (threadIdx.x >> 5) * 64; // my warp's slice
    float*        red   = (float*)(smem + 200704);   // [2][16][48]
    unsigned short* hst = (unsigned short*)(smem + 206848);

    const int b  = blockIdx.x;
    const int t0 = threadIdx.x;
    const int w  = t0 >> 5, l = t0 & 31, tid = l & 3, gid = l >> 2;
    const int i0 = b * PB;

    // stage this block's weight fragments into smem (once)
    {
        const uint4* src = (const uint4*)(g_whpack + (size_t)b * 49152);
        uint4* dst = (uint4*)wp;
        for (int i = t0; i < 49152 / 4; i += NTHR) dst[i] = src[i];
    }
    __syncthreads();

    const unsigned int* wpw = wp + (size_t)(w * NFRAG) * KFRAG * 64; // my warp's frags
    float hprev = 0.f;                                               // h state (t0<16 lanes of warp 0)

    for (int t = 0; t < T_SEQ; ++t) {
        // ---- prefetch gx for this block's outputs (warp 0, off critical path) ----
        float xz = 0.f, xr = 0.f, xn = 0.f;
        if (t0 < PB) {
            const float* gxr = g_gx + (size_t)t * G_DIM + i0 + t0;
            asm volatile("ld.global.cg.f32 %0, [%1];"       : "=f"(xz) : "l"(gxr));
            asm volatile("ld.global.cg.f32 %0, [%1+8192];"  : "=f"(xr) : "l"(gxr));
            asm volatile("ld.global.cg.f32 %0, [%1+16384];" : "=f"(xn) : "l"(gxr));
        }

        // ---- acquire h(t-1) slice for this warp: poll only our 8 producers ----
        if (l < 8) {
            const int p = w * 8 + l;
            unsigned f;
            do {
                asm volatile("ld.acquire.gpu.u32 %0, [%1];" : "=r"(f)
                             : "l"(g_flag + p) : "memory");
            } while (f < (unsigned)t);
            const uint4* src = &g_hbuf[(t + 1) & 1][p][0];
            unsigned d0, d1, d2, d3, e0, e1, e2, e3;
            asm volatile("ld.global.cg.v4.u32 {%0,%1,%2,%3}, [%4];"
                         : "=r"(d0), "=r"(d1), "=r"(d2), "=r"(d3) : "l"(src));
            asm volatile("ld.global.cg.v4.u32 {%0,%1,%2,%3}, [%4];"
                         : "=r"(e0), "=r"(e1), "=r"(e2), "=r"(e3) : "l"(src + 1));
            unsigned int* dst = h16sw + l * 8;
            dst[0] = d0; dst[1] = d1; dst[2] = d2; dst[3] = d3;
            dst[4] = e0; dst[5] = e1; dst[6] = e2; dst[7] = e3;
        }
        __syncwarp();

        // ---- mma: 48 cols x 128 k per warp ----
        float acc[NFRAG][4];
#pragma unroll
        for (int nf = 0; nf < NFRAG; ++nf)
#pragma unroll
            for (int q = 0; q < 4; ++q) acc[nf][q] = 0.f;

#pragma unroll
        for (int kf = 0; kf < KFRAG; ++kf) {
            unsigned a0 = h16sw[kf * 8 + tid];
            unsigned a2 = h16sw[kf * 8 + 4 + tid];
#pragma unroll
            for (int nf = 0; nf < NFRAG; ++nf) {
                const uint2 bb = *(const uint2*)(wpw + (size_t)((nf * KFRAG + kf) * 32 + l) * 2);
                asm volatile(
                    "mma.sync.aligned.m16n8k16.row.col.f32.f16.f16.f32 "
                    "{%0,%1,%2,%3},{%4,%5,%6,%7},{%8,%9},{%0,%1,%2,%3};"
                    : "+f"(acc[nf][0]), "+f"(acc[nf][1]), "+f"(acc[nf][2]), "+f"(acc[nf][3])
                    : "r"(a0), "r"(0u), "r"(a2), "r"(0u), "r"(bb.x), "r"(bb.y));
            }
        }

        // ---- write partials (double-buffered) ----
        float* redp = red + (t & 1) * 768 + w * 48;
        if (gid == 0) {
#pragma unroll
            for (int nf = 0; nf < NFRAG; ++nf) {
                redp[nf * 8 + 2 * tid]     = acc[nf][0];
                redp[nf * 8 + 2 * tid + 1] = acc[nf][1];
            }
        }
        __syncthreads();   // the ONLY block-wide sync per step

        // ---- reduce + activation + publish (warp 0, lanes 0..15) ----
        if (t0 < PB) {
            const float* rp = red + (t & 1) * 768;
            float sz = 0.f, sr = 0.f, sn = 0.f;
#pragma unroll
            for (int ww = 0; ww < NWARP; ++ww) {
                sz += rp[ww * 48 + t0];
                sr += rp[ww * 48 + 16 + t0];
                sn += rp[ww * 48 + 32 + t0];
            }
            float z    = 1.f / (1.f + __expf(-(xz + sz)));
            float r    = 1.f / (1.f + __expf(-(xr + sr)));
            float e2   = __expf(-2.f * (xn + r * sn));
            float cand = (1.f - e2) / (1.f + e2);
            float hn   = hprev + z * (cand - hprev);
            hprev = hn;
            out[(size_t)t * N_DIM + i0 + t0] = hn;
            hst[t0] = __half_as_ushort(__float2half(hn));
        }
        __syncwarp();
        if (t0 == 0) {
            uint4 d0 = *(const uint4*)hst;
            uint4 d1 = *((const uint4*)hst + 1);
            uint4* dst = &g_hbuf[t & 1][b][0];
            asm volatile("st.global.v4.u32 [%0], {%1,%2,%3,%4};"
                         :: "l"(dst), "r"(d0.x), "r"(d0.y), "r"(d0.z), "r"(d0.w) : "memory");
            asm volatile("st.global.v4.u32 [%0], {%1,%2,%3,%4};"
                         :: "l"(dst + 1), "r"(d1.x), "r"(d1.y), "r"(d1.z), "r"(d1.w) : "memory");
            asm volatile("st.release.gpu.u32 [%0], %1;"
                         :: "l"(g_flag + b), "r"((unsigned)(t + 1)) : "memory");
        }
    }
}

// ---------------- launcher ----------------
extern "C" void kernel_launch(void* const* d_in, const int* in_sizes, int n_in,
                              void* d_out, int out_size) {
    const float* x    = (const float*)d_in[0];
    const float* Wx   = (const float*)d_in[1];
    const float* Wh   = (const float*)d_in[2];
    const float* bias = (const float*)d_in[3];
    float* out = (float*)d_out;

    cudaFuncSetAttribute(gru_scan, cudaFuncAttributeMaxDynamicSharedMemorySize, SMEM_SCAN);

    reset_k<<<1, 256>>>();
    conv_x<<<4096, 256>>>(x);
    {
        int n = N_DIM * G_DIM;
        conv_wxt<<<(n + 255) / 256, 256>>>(Wx);
    }
    {
        int n = NBLK * NWARP * NFRAG * KFRAG * 32 * 2;
        pack_wh<<<(n + 255) / 256, 256>>>(Wh);
    }
    gemm_gx<<<dim3(G_DIM / 128, T_SEQ / 128), 256>>>(bias);
    gru_scan<<<NBLK, NTHR, SMEM_SCAN>>>(out);
}

// round 3
// speedup vs baseline: 3.0037x; 3.0037x over previous
#include <cuda_runtime.h>
#include <cuda_fp16.h>
#include <cstdint>

#define N_DIM  2048
#define T_SEQ  8192
#define G_DIM  6144
#define NBLK   128     // persistent blocks (1 per SM, all resident)
#define NTHR   512
#define NWARP  16
#define PB     16      // output elements per block
#define NFRAG  6       // n-fragments of 8 cols (48 cols per block)
#define KFRAG  8       // k-fragments of 16 per warp (128 k per warp)

// ---- scratch (device globals: allocation-free rule) ----
__device__ __half        g_x16[(size_t)T_SEQ * N_DIM];          // 32 MB
__device__ __half        g_WxT16[(size_t)G_DIM * N_DIM];        // 25 MB (transposed: [n][k])
__device__ float         g_gx[(size_t)T_SEQ * G_DIM];           // 192 MB
__device__ unsigned int  g_whpack[NBLK * NWARP * NFRAG * KFRAG * 32 * 2]; // 25 MB packed B-frags
__device__ __half        g_h16[2][N_DIM];                       // double-buffered h broadcast
__device__ unsigned int  g_ctr;                                 // grid barrier counter

// ---------------- reset ----------------
__global__ void reset_k() {
    if (threadIdx.x == 0) g_ctr = 0u;
    for (int i = threadIdx.x; i < 2 * N_DIM; i += blockDim.x)
        ((__half*)g_h16)[i] = __float2half(0.f);
}

// ---------------- convert x -> fp16 ----------------
__global__ void conv_x(const float* __restrict__ x) {
    const float2* x2 = (const float2*)x;
    __half2* o = (__half2*)g_x16;
    size_t n = (size_t)T_SEQ * N_DIM / 2;
    for (size_t i = blockIdx.x * (size_t)blockDim.x + threadIdx.x; i < n;
         i += (size_t)gridDim.x * blockDim.x)
        o[i] = __float22half2_rn(x2[i]);
}

// ------------- convert+transpose Wx -> WxT fp16 [n][k] -------------
__global__ void conv_wxt(const float* __restrict__ Wx) {
    size_t idx = blockIdx.x * (size_t)blockDim.x + threadIdx.x; // over K*G
    if (idx >= (size_t)N_DIM * G_DIM) return;
    int k = (int)(idx / G_DIM);
    int j = (int)(idx % G_DIM);
    g_WxT16[(size_t)j * N_DIM + k] = __float2half(Wx[idx]);
}

// ------------- pack Wh into per-block mma B fragments (fp16) -------------
// pidx = ((((b*16 + w)*6 + nf)*8 + kf)*32 + lane)*2 + r
__global__ void pack_wh(const float* __restrict__ Wh) {
    int idx = blockIdx.x * blockDim.x + threadIdx.x;
    if (idx >= NBLK * NWARP * NFRAG * KFRAG * 32 * 2) return;
    int r    = idx & 1;
    int l    = (idx >> 1) & 31;
    int kf   = (idx >> 6) & 7;
    int rest = idx >> 9;           // (b*16 + w)*6 + nf
    int nf   = rest % 6;
    int bw   = rest / 6;
    int w    = bw & 15;
    int b    = bw >> 4;
    int tid  = l & 3, gid = l >> 2;
    int grp  = nf >> 1;                                  // 0:z 1:r 2:n
    int j    = grp * N_DIM + b * PB + (nf & 1) * 8 + gid; // global column
    int k    = w * 128 + kf * 16 + r * 8 + 2 * tid;       // global k
    __half2 h;
    h.x = __float2half(Wh[(size_t)k * G_DIM + j]);
    h.y = __float2half(Wh[(size_t)(k + 1) * G_DIM + j]);
    g_whpack[idx] = *(unsigned int*)&h;
}

// ---------------- gx = x @ Wx + b  (fp16 mma, fp32 accum) ----------------
__global__ void __launch_bounds__(256) gemm_gx(const float* __restrict__ bias) {
    __shared__ __half As[128 * 40];
    __shared__ __half Bs[128 * 40];
    const int m0 = blockIdx.y * 128, n0 = blockIdx.x * 128;
    const int t = threadIdx.x, w = t >> 5, l = t & 31, tid = l & 3, gid = l >> 2;
    const int wm = w & 3, wn = w >> 2;
    float acc[2][8][4];
#pragma unroll
    for (int mt = 0; mt < 2; ++mt)
#pragma unroll
        for (int nt = 0; nt < 8; ++nt)
#pragma unroll
            for (int q = 0; q < 4; ++q) acc[mt][nt][q] = 0.f;

    for (int kt = 0; kt < N_DIM; kt += 32) {
        {
            int r = t >> 2, c = (t & 3) * 8;
            *(uint4*)(As + r * 40 + c)        = *(const uint4*)(g_x16  + (size_t)(m0 + r)      * N_DIM + kt + c);
            *(uint4*)(As + (r + 64) * 40 + c) = *(const uint4*)(g_x16  + (size_t)(m0 + r + 64) * N_DIM + kt + c);
            *(uint4*)(Bs + r * 40 + c)        = *(const uint4*)(g_WxT16 + (size_t)(n0 + r)      * N_DIM + kt + c);
            *(uint4*)(Bs + (r + 64) * 40 + c) = *(const uint4*)(g_WxT16 + (size_t)(n0 + r + 64) * N_DIM + kt + c);
        }
        __syncthreads();
#pragma unroll
        for (int s = 0; s < 2; ++s) {
            const int ko = s * 16;
            unsigned a[2][4];
#pragma unroll
            for (int mt = 0; mt < 2; ++mt) {
                int rb = wm * 32 + mt * 16;
                a[mt][0] = *(const unsigned*)(As + (rb + gid)     * 40 + ko + 2 * tid);
                a[mt][1] = *(const unsigned*)(As + (rb + gid + 8) * 40 + ko + 2 * tid);
                a[mt][2] = *(const unsigned*)(As + (rb + gid)     * 40 + ko + 2 * tid + 8);
                a[mt][3] = *(const unsigned*)(As + (rb + gid + 8) * 40 + ko + 2 * tid + 8);
            }
#pragma unroll
            for (int nt = 0; nt < 8; ++nt) {
                int cb = wn * 64 + nt * 8 + gid;
                unsigned b0 = *(const unsigned*)(Bs + cb * 40 + ko + 2 * tid);
                unsigned b1 = *(const unsigned*)(Bs + cb * 40 + ko + 2 * tid + 8);
#pragma unroll
                for (int mt = 0; mt < 2; ++mt) {
                    asm volatile(
                        "mma.sync.aligned.m16n8k16.row.col.f32.f16.f16.f32 "
                        "{%0,%1,%2,%3},{%4,%5,%6,%7},{%8,%9},{%0,%1,%2,%3};"
                        : "+f"(acc[mt][nt][0]), "+f"(acc[mt][nt][1]),
                          "+f"(acc[mt][nt][2]), "+f"(acc[mt][nt][3])
                        : "r"(a[mt][0]), "r"(a[mt][1]), "r"(a[mt][2]), "r"(a[mt][3]),
                          "r"(b0), "r"(b1));
                }
            }
        }
        __syncthreads();
    }
#pragma unroll
    for (int mt = 0; mt < 2; ++mt)
#pragma unroll
        for (int nt = 0; nt < 8; ++nt) {
            int row = m0 + wm * 32 + mt * 16 + gid;
            int col = n0 + wn * 64 + nt * 8 + 2 * tid;
            float b0v = __ldg(bias + col), b1v = __ldg(bias + col + 1);
            g_gx[(size_t)row * G_DIM + col]           = acc[mt][nt][0] + b0v;
            g_gx[(size_t)row * G_DIM + col + 1]       = acc[mt][nt][1] + b1v;
            g_gx[(size_t)(row + 8) * G_DIM + col]     = acc[mt][nt][2] + b0v;
            g_gx[(size_t)(row + 8) * G_DIM + col + 1] = acc[mt][nt][3] + b1v;
        }
}

// ---------------- persistent GRU scan ----------------
// dynamic smem layout (bytes):
//   [0,196608)        packed Wh fragments (49152 u32)
//   [196608,200704)   h16s: per-warp h slice, 16 warps x 64 u32 (256B each)
//   [200704,206848)   red[2][16][48] f32 (double-buffered partials)
#define SMEM_SCAN 206848

__global__ void __launch_bounds__(NTHR, 1) gru_scan(float* __restrict__ out) {
    extern __shared__ unsigned char smem[];
    unsigned int* wp    = (unsigned int*)smem;
    unsigned int* h16sw = (unsigned int*)(smem + 196608) + (threadIdx.x >> 5) * 64; // my warp's slice
    float*        red   = (float*)(smem + 200704);   // [2][16][48]

    const int b  = blockIdx.x;
    const int t0 = threadIdx.x;
    const int w  = t0 >> 5, l = t0 & 31, tid = l & 3, gid = l >> 2;
    const int i0 = b * PB;

    // stage this block's weight fragments into smem (once)
    {
        const uint4* src = (const uint4*)(g_whpack + (size_t)b * 49152);
        uint4* dst = (uint4*)wp;
        for (int i = t0; i < 49152 / 4; i += NTHR) dst[i] = src[i];
    }
    __syncthreads();

    const unsigned int* wpw = wp + (size_t)(w * NFRAG) * KFRAG * 64; // my warp's frags
    float hprev = 0.f;                                               // h state (lanes 0..15 of warp 0)

    for (int t = 0; t < T_SEQ; ++t) {
        // ---- prefetch gx for this block's outputs (warp 0, consumed ~2000cyc later) ----
        float xa = 0.f, xb = 0.f;   // low lanes: xz, xn ; high lanes: xr
        if (w == 0) {
            const float* base = g_gx + (size_t)t * G_DIM + i0 + (l & 15);
            if (l < 16) {
                xa = __ldg(base);
                xb = __ldg(base + 2 * N_DIM);
            } else {
                xa = __ldg(base + N_DIM);
            }
        }

        // ---- per-warp h(t) slice load: L2-strong, no block barrier needed ----
        {
            const unsigned* hg = (const unsigned*)(g_h16[t & 1]);
            unsigned ha, hb;
            asm volatile("ld.global.cg.u32 %0, [%1];" : "=r"(ha) : "l"(hg + w * 64 + l));
            asm volatile("ld.global.cg.u32 %0, [%1];" : "=r"(hb) : "l"(hg + w * 64 + 32 + l));
            h16sw[l]      = ha;
            h16sw[32 + l] = hb;
        }
        __syncwarp();

        // ---- mma: 48 cols x 128 k per warp ----
        float acc[NFRAG][4];
#pragma unroll
        for (int nf = 0; nf < NFRAG; ++nf)
#pragma unroll
            for (int q = 0; q < 4; ++q) acc[nf][q] = 0.f;

#pragma unroll
        for (int kf = 0; kf < KFRAG; ++kf) {
            unsigned a0 = h16sw[kf * 8 + tid];
            unsigned a2 = h16sw[kf * 8 + 4 + tid];
#pragma unroll
            for (int nf = 0; nf < NFRAG; ++nf) {
                const uint2 bb = *(const uint2*)(wpw + (size_t)((nf * KFRAG + kf) * 32 + l) * 2);
                asm volatile(
                    "mma.sync.aligned.m16n8k16.row.col.f32.f16.f16.f32 "
                    "{%0,%1,%2,%3},{%4,%5,%6,%7},{%8,%9},{%0,%1,%2,%3};"
                    : "+f"(acc[nf][0]), "+f"(acc[nf][1]), "+f"(acc[nf][2]), "+f"(acc[nf][3])
                    : "r"(a0), "r"(0u), "r"(a2), "r"(0u), "r"(bb.x), "r"(bb.y));
            }
        }

        // ---- write partials (double-buffered by t&1) ----
        float* redp = red + (t & 1) * 768 + w * 48;
        if (gid == 0) {
#pragma unroll
            for (int nf = 0; nf < NFRAG; ++nf) {
                *(float2*)(redp + nf * 8 + 2 * tid) = make_float2(acc[nf][0], acc[nf][1]);
            }
        }
        __syncthreads();   // S2: partials visible to warp 0

        // ---- reduce + activation + publish (warp 0, all 32 lanes) ----
        if (w == 0) {
            const float* rp = red + (t & 1) * 768;
            float sa = 0.f, sb = 0.f;
#pragma unroll
            for (int ww = 0; ww < NWARP; ++ww) {
                sa += rp[ww * 48 + l];              // low: z-partials, high: r-partials
                sb += rp[ww * 48 + 32 + (l & 15)];  // n-partials
            }
            float pre = xa + sa;
            float sig = __fdividef(1.f, 1.f + __expf(-pre));   // low: z, high: r
            float r   = __shfl_sync(0xffffffffu, sig, (l + 16) & 31);
            float ci  = xb + r * sb;
            ci = fminf(fmaxf(ci, -15.f), 15.f);
            float e2  = __expf(2.f * ci);
            float cand = __fdividef(e2 - 1.f, e2 + 1.f);
            if (l < 16) {
                float hn = fmaf(sig, cand - hprev, hprev);
                hprev = hn;
                out[(size_t)t * N_DIM + i0 + l] = hn;
                g_h16[(t + 1) & 1][i0 + l] = __float2half(hn);
            }
            __syncwarp();
            if (l == 0 && t < T_SEQ - 1) {
                unsigned target = (unsigned)(NBLK * (t + 1));
                asm volatile("red.release.gpu.add.u32 [%0], %1;" :: "l"(&g_ctr), "r"(1u) : "memory");
                unsigned v;
                do {
                    asm volatile("ld.acquire.gpu.u32 %0, [%1];" : "=r"(v) : "l"(&g_ctr) : "memory");
                } while (v < target);
            }
        }
        __syncthreads();   // S3: release block into next step (h(t) globally complete)
    }
}

// ---------------- launcher ----------------
extern "C" void kernel_launch(void* const* d_in, const int* in_sizes, int n_in,
                              void* d_out, int out_size) {
    const float* x    = (const float*)d_in[0];
    const float* Wx   = (const float*)d_in[1];
    const float* Wh   = (const float*)d_in[2];
    const float* bias = (const float*)d_in[3];
    float* out = (float*)d_out;

    cudaFuncSetAttribute(gru_scan, cudaFuncAttributeMaxDynamicSharedMemorySize, SMEM_SCAN);

    reset_k<<<1, 256>>>();
    conv_x<<<4096, 256>>>(x);
    {
        int n = N_DIM * G_DIM;
        conv_wxt<<<(n + 255) / 256, 256>>>(Wx);
    }
    {
        int n = NBLK * NWARP * NFRAG * KFRAG * 32 * 2;
        pack_wh<<<(n + 255) / 256, 256>>>(Wh);
    }
    gemm_gx<<<dim3(G_DIM / 128, T_SEQ / 128), 256>>>(bias);
    gru_scan<<<NBLK, NTHR, SMEM_SCAN>>>(out);
}

// round 4
// speedup vs baseline: 4.0738x; 1.3563x over previous
#include <cuda_runtime.h>
#include <cuda_fp16.h>
#include <cstdint>

#define N_DIM  2048
#define T_SEQ  8192
#define G_DIM  6144
#define NBLK   128     // persistent blocks (1 per SM, all resident)
#define NTHR   512
#define NWARP  16
#define PB     16      // output elements per block
#define NFRAG  6       // n-fragments of 8 cols (48 cols per block)
#define KFRAG  8       // k-fragments of 16 per warp (128 k per warp)

// ---- scratch (device globals: allocation-free rule) ----
__device__ __half        g_x16[(size_t)T_SEQ * N_DIM];          // 32 MB
__device__ __half        g_WxT16[(size_t)G_DIM * N_DIM];        // 25 MB (transposed: [n][k])
__device__ float         g_gx[(size_t)T_SEQ * G_DIM];           // 192 MB
__device__ unsigned int  g_whpack[NBLK * NWARP * NFRAG * KFRAG * 32 * 2]; // 25 MB packed B-frags
__device__ __half        g_h16[2][N_DIM];                       // double-buffered h broadcast
__device__ unsigned int  g_ctr;                                 // grid barrier counter

// ---------------- reset ----------------
__global__ void reset_k() {
    if (threadIdx.x == 0) g_ctr = 0u;
    for (int i = threadIdx.x; i < 2 * N_DIM; i += blockDim.x)
        ((__half*)g_h16)[i] = __float2half(0.f);
}

// ---------------- convert x -> fp16 ----------------
__global__ void conv_x(const float* __restrict__ x) {
    const float2* x2 = (const float2*)x;
    __half2* o = (__half2*)g_x16;
    size_t n = (size_t)T_SEQ * N_DIM / 2;
    for (size_t i = blockIdx.x * (size_t)blockDim.x + threadIdx.x; i < n;
         i += (size_t)gridDim.x * blockDim.x)
        o[i] = __float22half2_rn(x2[i]);
}

// ------------- convert+transpose Wx -> WxT fp16 [n][k] -------------
__global__ void conv_wxt(const float* __restrict__ Wx) {
    size_t idx = blockIdx.x * (size_t)blockDim.x + threadIdx.x; // over K*G
    if (idx >= (size_t)N_DIM * G_DIM) return;
    int k = (int)(idx / G_DIM);
    int j = (int)(idx % G_DIM);
    g_WxT16[(size_t)j * N_DIM + k] = __float2half(Wx[idx]);
}

// ------------- pack Wh into per-block mma B fragments (fp16) -------------
// pidx = ((((b*16 + w)*6 + nf)*8 + kf)*32 + lane)*2 + r
__global__ void pack_wh(const float* __restrict__ Wh) {
    int idx = blockIdx.x * blockDim.x + threadIdx.x;
    if (idx >= NBLK * NWARP * NFRAG * KFRAG * 32 * 2) return;
    int r    = idx & 1;
    int l    = (idx >> 1) & 31;
    int kf   = (idx >> 6) & 7;
    int rest = idx >> 9;           // (b*16 + w)*6 + nf
    int nf   = rest % 6;
    int bw   = rest / 6;
    int w    = bw & 15;
    int b    = bw >> 4;
    int tid  = l & 3, gid = l >> 2;
    int grp  = nf >> 1;                                  // 0:z 1:r 2:n
    int j    = grp * N_DIM + b * PB + (nf & 1) * 8 + gid; // global column
    int k    = w * 128 + kf * 16 + r * 8 + 2 * tid;       // global k
    __half2 h;
    h.x = __float2half(Wh[(size_t)k * G_DIM + j]);
    h.y = __float2half(Wh[(size_t)(k + 1) * G_DIM + j]);
    g_whpack[idx] = *(unsigned int*)&h;
}

// ---------------- gx = x @ Wx + b  (fp16 mma, fp32 accum) ----------------
__global__ void __launch_bounds__(256) gemm_gx(const float* __restrict__ bias) {
    __shared__ __half As[128 * 40];
    __shared__ __half Bs[128 * 40];
    const int m0 = blockIdx.y * 128, n0 = blockIdx.x * 128;
    const int t = threadIdx.x, w = t >> 5, l = t & 31, tid = l & 3, gid = l >> 2;
    const int wm = w & 3, wn = w >> 2;
    float acc[2][8][4];
#pragma unroll
    for (int mt = 0; mt < 2; ++mt)
#pragma unroll
        for (int nt = 0; nt < 8; ++nt)
#pragma unroll
            for (int q = 0; q < 4; ++q) acc[mt][nt][q] = 0.f;

    for (int kt = 0; kt < N_DIM; kt += 32) {
        {
            int r = t >> 2, c = (t & 3) * 8;
            *(uint4*)(As + r * 40 + c)        = *(const uint4*)(g_x16  + (size_t)(m0 + r)      * N_DIM + kt + c);
            *(uint4*)(As + (r + 64) * 40 + c) = *(const uint4*)(g_x16  + (size_t)(m0 + r + 64) * N_DIM + kt + c);
            *(uint4*)(Bs + r * 40 + c)        = *(const uint4*)(g_WxT16 + (size_t)(n0 + r)      * N_DIM + kt + c);
            *(uint4*)(Bs + (r + 64) * 40 + c) = *(const uint4*)(g_WxT16 + (size_t)(n0 + r + 64) * N_DIM + kt + c);
        }
        __syncthreads();
#pragma unroll
        for (int s = 0; s < 2; ++s) {
            const int ko = s * 16;
            unsigned a[2][4];
#pragma unroll
            for (int mt = 0; mt < 2; ++mt) {
                int rb = wm * 32 + mt * 16;
                a[mt][0] = *(const unsigned*)(As + (rb + gid)     * 40 + ko + 2 * tid);
                a[mt][1] = *(const unsigned*)(As + (rb + gid + 8) * 40 + ko + 2 * tid);
                a[mt][2] = *(const unsigned*)(As + (rb + gid)     * 40 + ko + 2 * tid + 8);
                a[mt][3] = *(const unsigned*)(As + (rb + gid + 8) * 40 + ko + 2 * tid + 8);
            }
#pragma unroll
            for (int nt = 0; nt < 8; ++nt) {
                int cb = wn * 64 + nt * 8 + gid;
                unsigned b0 = *(const unsigned*)(Bs + cb * 40 + ko + 2 * tid);
                unsigned b1 = *(const unsigned*)(Bs + cb * 40 + ko + 2 * tid + 8);
#pragma unroll
                for (int mt = 0; mt < 2; ++mt) {
                    asm volatile(
                        "mma.sync.aligned.m16n8k16.row.col.f32.f16.f16.f32 "
                        "{%0,%1,%2,%3},{%4,%5,%6,%7},{%8,%9},{%0,%1,%2,%3};"
                        : "+f"(acc[mt][nt][0]), "+f"(acc[mt][nt][1]),
                          "+f"(acc[mt][nt][2]), "+f"(acc[mt][nt][3])
                        : "r"(a[mt][0]), "r"(a[mt][1]), "r"(a[mt][2]), "r"(a[mt][3]),
                          "r"(b0), "r"(b1));
                }
            }
        }
        __syncthreads();
    }
#pragma unroll
    for (int mt = 0; mt < 2; ++mt)
#pragma unroll
        for (int nt = 0; nt < 8; ++nt) {
            int row = m0 + wm * 32 + mt * 16 + gid;
            int col = n0 + wn * 64 + nt * 8 + 2 * tid;
            float b0v = __ldg(bias + col), b1v = __ldg(bias + col + 1);
            g_gx[(size_t)row * G_DIM + col]           = acc[mt][nt][0] + b0v;
            g_gx[(size_t)row * G_DIM + col + 1]       = acc[mt][nt][1] + b1v;
            g_gx[(size_t)(row + 8) * G_DIM + col]     = acc[mt][nt][2] + b0v;
            g_gx[(size_t)(row + 8) * G_DIM + col + 1] = acc[mt][nt][3] + b1v;
        }
}

// ---------------- persistent GRU scan (R1 topology, trimmed tail) ----------------
// dynamic smem layout (bytes):
//   [0,196608)      packed Wh fragments (49152 u32)
//   [196608,200704) h16s broadcast (1024 u32)
//   [200704,203776) red[16][48] f32
//   [203776,203968) gh[48] f32
//   [203968,204000) hst[16] u16 (publish staging)
#define SMEM_SCAN 204032

__global__ void __launch_bounds__(NTHR, 1) gru_scan(float* __restrict__ out) {
    extern __shared__ unsigned char smem[];
    unsigned int*   wp   = (unsigned int*)smem;
    unsigned int*   h16s = (unsigned int*)(smem + 196608);
    float*          red  = (float*)(smem + 200704);
    float*          gh   = (float*)(smem + 203776);
    unsigned short* hst  = (unsigned short*)(smem + 203968);

    const int b  = blockIdx.x;
    const int t0 = threadIdx.x;
    const int w  = t0 >> 5, l = t0 & 31, tid = l & 3, gid = l >> 2;
    const int i0 = b * PB;

    // stage this block's weight fragments into smem (once)
    {
        const uint4* src = (const uint4*)(g_whpack + (size_t)b * 49152);
        uint4* dst = (uint4*)wp;
        for (int i = t0; i < 49152 / 4; i += NTHR) dst[i] = src[i];
    }
    __syncthreads();

    float hprev = 0.f;   // h state, live in warp 0 lanes 0..15

    for (int t = 0; t < T_SEQ; ++t) {
        // ---- gx prefetch for this block's outputs (warp 0, consumed much later) ----
        float xz = 0.f, xr = 0.f, xn = 0.f;
        if (t0 < PB) {
            const float* gxr = g_gx + (size_t)t * G_DIM + i0 + t0;
            xz = __ldg(gxr);
            xr = __ldg(gxr + N_DIM);
            xn = __ldg(gxr + 2 * N_DIM);
        }
        // ---- cooperative h broadcast: one 8B L2-coherent load per thread ----
        {
            const uint2* hg = (const uint2*)(g_h16[t & 1]);
            unsigned v0, v1;
            asm volatile("ld.global.cg.v2.u32 {%0,%1}, [%2];"
                         : "=r"(v0), "=r"(v1) : "l"(hg + t0));
            ((uint2*)h16s)[t0] = make_uint2(v0, v1);
        }
        __syncthreads();   // B1

        // ---- mma: 48 cols x 128 k per warp ----
        float acc[NFRAG][4];
#pragma unroll
        for (int nf = 0; nf < NFRAG; ++nf)
#pragma unroll
            for (int q = 0; q < 4; ++q) acc[nf][q] = 0.f;

#pragma unroll
        for (int kf = 0; kf < KFRAG; ++kf) {
            unsigned a0 = h16s[w * 64 + kf * 8 + tid];
            unsigned a2 = h16s[w * 64 + kf * 8 + 4 + tid];
#pragma unroll
            for (int nf = 0; nf < NFRAG; ++nf) {
                const uint2 bb = *(const uint2*)(wp + (size_t)(((w * NFRAG + nf) * KFRAG + kf) * 32 + l) * 2);
                asm volatile(
                    "mma.sync.aligned.m16n8k16.row.col.f32.f16.f16.f32 "
                    "{%0,%1,%2,%3},{%4,%5,%6,%7},{%8,%9},{%0,%1,%2,%3};"
                    : "+f"(acc[nf][0]), "+f"(acc[nf][1]), "+f"(acc[nf][2]), "+f"(acc[nf][3])
                    : "r"(a0), "r"(0u), "r"(a2), "r"(0u), "r"(bb.x), "r"(bb.y));
            }
        }
        if (gid == 0) {
#pragma unroll
            for (int nf = 0; nf < NFRAG; ++nf)
                *(float2*)(red + w * 48 + nf * 8 + 2 * tid) = make_float2(acc[nf][0], acc[nf][1]);
        }
        __syncthreads();   // B2

        if (t0 < 48) {
            float s = 0.f;
#pragma unroll
            for (int ww = 0; ww < NWARP; ++ww) s += red[ww * 48 + t0];
            gh[t0] = s;
        }
        __syncthreads();   // B3

        // ---- activation + publish + grid barrier (warp 0 only) ----
        if (w == 0) {
            if (l < PB) {
                float z    = __fdividef(1.f, 1.f + __expf(-(xz + gh[l])));
                float r    = __fdividef(1.f, 1.f + __expf(-(xr + gh[16 + l])));
                float ci   = xn + r * gh[32 + l];
                ci = fminf(fmaxf(ci, -15.f), 15.f);
                float e2   = __expf(2.f * ci);
                float cand = __fdividef(e2 - 1.f, e2 + 1.f);
                float hn   = fmaf(z, cand - hprev, hprev);
                hprev = hn;
                out[(size_t)t * N_DIM + i0 + l] = hn;
                hst[l] = __half_as_ushort(__float2half(hn));
            }
            __syncwarp();
            if (l == 0) {
                uint4 d0 = *(const uint4*)hst;
                uint4 d1 = *((const uint4*)hst + 1);
                uint4* dst = (uint4*)(g_h16[(t + 1) & 1] + i0);
                asm volatile("st.global.v4.u32 [%0], {%1,%2,%3,%4};"
                             :: "l"(dst), "r"(d0.x), "r"(d0.y), "r"(d0.z), "r"(d0.w) : "memory");
                asm volatile("st.global.v4.u32 [%0], {%1,%2,%3,%4};"
                             :: "l"(dst + 1), "r"(d1.x), "r"(d1.y), "r"(d1.z), "r"(d1.w) : "memory");
                if (t < T_SEQ - 1) {
                    unsigned target = (unsigned)(NBLK * (t + 1));
                    asm volatile("red.release.gpu.add.u32 [%0], %1;" :: "l"(&g_ctr), "r"(1u) : "memory");
                    unsigned v;
                    do {
                        asm volatile("ld.acquire.gpu.u32 %0, [%1];" : "=r"(v) : "l"(&g_ctr) : "memory");
                    } while (v < target);
                }
            }
        }
        __syncthreads();   // B4: all blocks' h(t) globally visible
    }
}

// ---------------- launcher ----------------
extern "C" void kernel_launch(void* const* d_in, const int* in_sizes, int n_in,
                              void* d_out, int out_size) {
    const float* x    = (const float*)d_in[0];
    const float* Wx   = (const float*)d_in[1];
    const float* Wh   = (const float*)d_in[2];
    const float* bias = (const float*)d_in[3];
    float* out = (float*)d_out;

    cudaFuncSetAttribute(gru_scan, cudaFuncAttributeMaxDynamicSharedMemorySize, SMEM_SCAN);

    reset_k<<<1, 256>>>();
    conv_x<<<4096, 256>>>(x);
    {
        int n = N_DIM * G_DIM;
        conv_wxt<<<(n + 255) / 256, 256>>>(Wx);
    }
    {
        int n = NBLK * NWARP * NFRAG * KFRAG * 32 * 2;
        pack_wh<<<(n + 255) / 256, 256>>>(Wh);
    }
    gemm_gx<<<dim3(G_DIM / 128, T_SEQ / 128), 256>>>(bias);
    gru_scan<<<NBLK, NTHR, SMEM_SCAN>>>(out);
}

// round 5
// speedup vs baseline: 4.2914x; 1.0534x over previous
#include <cuda_runtime.h>
#include <cuda_fp16.h>
#include <cstdint>

#define N_DIM  2048
#define T_SEQ  8192
#define G_DIM  6144
#define NBLK   128     // persistent blocks (1 per SM, all resident)
#define NTHR   512
#define NWARP  16
#define PB     16      // output elements per block
#define NFRAG  6       // n-fragments of 8 cols (48 cols per block)
#define KFRAG  8       // k-fragments of 16 per warp (128 k per warp)
#define KREG   4       // kf 0..3 register-resident, kf 4..7 smem-resident

// ---- scratch (device globals: allocation-free rule) ----
__device__ __half        g_x16[(size_t)T_SEQ * N_DIM];          // 32 MB
__device__ __half        g_WxT16[(size_t)G_DIM * N_DIM];        // 25 MB (transposed: [n][k])
__device__ float         g_gx[(size_t)T_SEQ * G_DIM];           // 192 MB
__device__ unsigned int  g_whpack[NBLK * NWARP * NFRAG * KFRAG * 32 * 2]; // 25 MB packed B-frags
__device__ __half        g_h16[2][N_DIM];                       // double-buffered h broadcast
__device__ unsigned int  g_ctr;                                 // grid barrier counter

// ---------------- reset ----------------
__global__ void reset_k() {
    if (threadIdx.x == 0) g_ctr = 0u;
    for (int i = threadIdx.x; i < 2 * N_DIM; i += blockDim.x)
        ((__half*)g_h16)[i] = __float2half(0.f);
}

// ---------------- convert x -> fp16 ----------------
__global__ void conv_x(const float* __restrict__ x) {
    const float2* x2 = (const float2*)x;
    __half2* o = (__half2*)g_x16;
    size_t n = (size_t)T_SEQ * N_DIM / 2;
    for (size_t i = blockIdx.x * (size_t)blockDim.x + threadIdx.x; i < n;
         i += (size_t)gridDim.x * blockDim.x)
        o[i] = __float22half2_rn(x2[i]);
}

// ------------- convert+transpose Wx -> WxT fp16 [n][k] -------------
__global__ void conv_wxt(const float* __restrict__ Wx) {
    size_t idx = blockIdx.x * (size_t)blockDim.x + threadIdx.x; // over K*G
    if (idx >= (size_t)N_DIM * G_DIM) return;
    int k = (int)(idx / G_DIM);
    int j = (int)(idx % G_DIM);
    g_WxT16[(size_t)j * N_DIM + k] = __float2half(Wx[idx]);
}

// ------------- pack Wh into per-block mma B fragments (fp16) -------------
// pidx = ((((b*16 + w)*6 + nf)*8 + kf)*32 + lane)*2 + r
__global__ void pack_wh(const float* __restrict__ Wh) {
    int idx = blockIdx.x * blockDim.x + threadIdx.x;
    if (idx >= NBLK * NWARP * NFRAG * KFRAG * 32 * 2) return;
    int r    = idx & 1;
    int l    = (idx >> 1) & 31;
    int kf   = (idx >> 6) & 7;
    int rest = idx >> 9;           // (b*16 + w)*6 + nf
    int nf   = rest % 6;
    int bw   = rest / 6;
    int w    = bw & 15;
    int b    = bw >> 4;
    int tid  = l & 3, gid = l >> 2;
    int grp  = nf >> 1;                                  // 0:z 1:r 2:n
    int j    = grp * N_DIM + b * PB + (nf & 1) * 8 + gid; // global column
    int k    = w * 128 + kf * 16 + r * 8 + 2 * tid;       // global k
    __half2 h;
    h.x = __float2half(Wh[(size_t)k * G_DIM + j]);
    h.y = __float2half(Wh[(size_t)(k + 1) * G_DIM + j]);
    g_whpack[idx] = *(unsigned int*)&h;
}

// ---------------- gx = x @ Wx + b  (fp16 mma, fp32 accum) ----------------
__global__ void __launch_bounds__(256) gemm_gx(const float* __restrict__ bias) {
    __shared__ __half As[128 * 40];
    __shared__ __half Bs[128 * 40];
    const int m0 = blockIdx.y * 128, n0 = blockIdx.x * 128;
    const int t = threadIdx.x, w = t >> 5, l = t & 31, tid = l & 3, gid = l >> 2;
    const int wm = w & 3, wn = w >> 2;
    float acc[2][8][4];
#pragma unroll
    for (int mt = 0; mt < 2; ++mt)
#pragma unroll
        for (int nt = 0; nt < 8; ++nt)
#pragma unroll
            for (int q = 0; q < 4; ++q) acc[mt][nt][q] = 0.f;

    for (int kt = 0; kt < N_DIM; kt += 32) {
        {
            int r = t >> 2, c = (t & 3) * 8;
            *(uint4*)(As + r * 40 + c)        = *(const uint4*)(g_x16  + (size_t)(m0 + r)      * N_DIM + kt + c);
            *(uint4*)(As + (r + 64) * 40 + c) = *(const uint4*)(g_x16  + (size_t)(m0 + r + 64) * N_DIM + kt + c);
            *(uint4*)(Bs + r * 40 + c)        = *(const uint4*)(g_WxT16 + (size_t)(n0 + r)      * N_DIM + kt + c);
            *(uint4*)(Bs + (r + 64) * 40 + c) = *(const uint4*)(g_WxT16 + (size_t)(n0 + r + 64) * N_DIM + kt + c);
        }
        __syncthreads();
#pragma unroll
        for (int s = 0; s < 2; ++s) {
            const int ko = s * 16;
            unsigned a[2][4];
#pragma unroll
            for (int mt = 0; mt < 2; ++mt) {
                int rb = wm * 32 + mt * 16;
                a[mt][0] = *(const unsigned*)(As + (rb + gid)     * 40 + ko + 2 * tid);
                a[mt][1] = *(const unsigned*)(As + (rb + gid + 8) * 40 + ko + 2 * tid);
                a[mt][2] = *(const unsigned*)(As + (rb + gid)     * 40 + ko + 2 * tid + 8);
                a[mt][3] = *(const unsigned*)(As + (rb + gid + 8) * 40 + ko + 2 * tid + 8);
            }
#pragma unroll
            for (int nt = 0; nt < 8; ++nt) {
                int cb = wn * 64 + nt * 8 + gid;
                unsigned b0 = *(const unsigned*)(Bs + cb * 40 + ko + 2 * tid);
                unsigned b1 = *(const unsigned*)(Bs + cb * 40 + ko + 2 * tid + 8);
#pragma unroll
                for (int mt = 0; mt < 2; ++mt) {
                    asm volatile(
                        "mma.sync.aligned.m16n8k16.row.col.f32.f16.f16.f32 "
                        "{%0,%1,%2,%3},{%4,%5,%6,%7},{%8,%9},{%0,%1,%2,%3};"
                        : "+f"(acc[mt][nt][0]), "+f"(acc[mt][nt][1]),
                          "+f"(acc[mt][nt][2]), "+f"(acc[mt][nt][3])
                        : "r"(a[mt][0]), "r"(a[mt][1]), "r"(a[mt][2]), "r"(a[mt][3]),
                          "r"(b0), "r"(b1));
                }
            }
        }
        __syncthreads();
    }
#pragma unroll
    for (int mt = 0; mt < 2; ++mt)
#pragma unroll
        for (int nt = 0; nt < 8; ++nt) {
            int row = m0 + wm * 32 + mt * 16 + gid;
            int col = n0 + wn * 64 + nt * 8 + 2 * tid;
            float b0v = __ldg(bias + col), b1v = __ldg(bias + col + 1);
            g_gx[(size_t)row * G_DIM + col]           = acc[mt][nt][0] + b0v;
            g_gx[(size_t)row * G_DIM + col + 1]       = acc[mt][nt][1] + b1v;
            g_gx[(size_t)(row + 8) * G_DIM + col]     = acc[mt][nt][2] + b0v;
            g_gx[(size_t)(row + 8) * G_DIM + col + 1] = acc[mt][nt][3] + b1v;
        }
}

// ---------------- persistent GRU scan (R4 topology + half-register-resident B) ----------------
// dynamic smem layout (bytes):
//   [0,98304)       packed Wh fragments, kf 4..7 only (24576 u32)
//   [98304,102400)  h16s broadcast (1024 u32)
//   [102400,105472) red[16][48] f32
//   [105472,105664) gh[48] f32
//   [105664,105696) hst[16] u16 (publish staging)
#define SMEM_SCAN 105728

__global__ void __launch_bounds__(NTHR, 1) gru_scan(float* __restrict__ out) {
    extern __shared__ unsigned char smem[];
    unsigned int*   wp   = (unsigned int*)smem;                 // kf 4..7 frags
    unsigned int*   h16s = (unsigned int*)(smem + 98304);
    float*          red  = (float*)(smem + 102400);
    float*          gh   = (float*)(smem + 105472);
    unsigned short* hst  = (unsigned short*)(smem + 105664);

    const int b  = blockIdx.x;
    const int t0 = threadIdx.x;
    const int w  = t0 >> 5, l = t0 & 31, tid = l & 3, gid = l >> 2;
    const int i0 = b * PB;

    // ---- load kf 0..3 B-fragments into registers (persistent) ----
    unsigned breg[NFRAG][KREG][2];
    {
        const unsigned* base = g_whpack + (size_t)b * 49152;
#pragma unroll
        for (int nf = 0; nf < NFRAG; ++nf)
#pragma unroll
            for (int kf = 0; kf < KREG; ++kf) {
                const uint2 v = *(const uint2*)(base + (size_t)(((w * NFRAG + nf) * KFRAG + kf) * 32 + l) * 2);
                breg[nf][kf][0] = v.x;
                breg[nf][kf][1] = v.y;
            }
    }
    // ---- stage kf 4..7 B-fragments into smem (once) ----
    {
        // smem index: ((w*NFRAG+nf)*4 + (kf-4))*64 + l*2  (contiguous repack)
        const unsigned* base = g_whpack + (size_t)b * 49152;
        for (int i = t0; i < NWARP * NFRAG * 4; i += NTHR) {
            int rest = i;                    // (w*6+nf)*4 + kq
            int kq   = rest & 3;
            int wn_  = rest >> 2;            // w*6+nf
            const uint4* s = (const uint4*)(base + (size_t)((wn_ * KFRAG + 4 + kq) * 32) * 2);
            uint4* d = (uint4*)(wp + (size_t)i * 64);
            // copy 64 u32 = 16 uint4 for this fragment, spread across... do per-thread full frag
#pragma unroll
            for (int q = 0; q < 16; ++q) d[q] = s[q];
        }
    }
    __syncthreads();

    float hprev = 0.f;   // h state, live in warp 0 lanes 0..15

    for (int t = 0; t < T_SEQ; ++t) {
        // ---- gx prefetch for this block's outputs (warp 0, consumed much later) ----
        float xz = 0.f, xr = 0.f, xn = 0.f;
        if (t0 < PB) {
            const float* gxr = g_gx + (size_t)t * G_DIM + i0 + t0;
            xz = __ldg(gxr);
            xr = __ldg(gxr + N_DIM);
            xn = __ldg(gxr + 2 * N_DIM);
        }
        // ---- cooperative h broadcast: one 8B L2-coherent load per thread ----
        {
            const uint2* hg = (const uint2*)(g_h16[t & 1]);
            unsigned v0, v1;
            asm volatile("ld.global.cg.v2.u32 {%0,%1}, [%2];"
                         : "=r"(v0), "=r"(v1) : "l"(hg + t0));
            ((uint2*)h16s)[t0] = make_uint2(v0, v1);
        }
        __syncthreads();   // B1

        // ---- mma: 48 cols x 128 k per warp; kf 0..3 from regs, 4..7 from smem ----
        float acc[NFRAG][4];
#pragma unroll
        for (int nf = 0; nf < NFRAG; ++nf)
#pragma unroll
            for (int q = 0; q < 4; ++q) acc[nf][q] = 0.f;

#pragma unroll
        for (int kf = 0; kf < KREG; ++kf) {
            unsigned a0 = h16s[w * 64 + kf * 8 + tid];
            unsigned a2 = h16s[w * 64 + kf * 8 + 4 + tid];
#pragma unroll
            for (int nf = 0; nf < NFRAG; ++nf) {
                asm volatile(
                    "mma.sync.aligned.m16n8k16.row.col.f32.f16.f16.f32 "
                    "{%0,%1,%2,%3},{%4,%5,%6,%7},{%8,%9},{%0,%1,%2,%3};"
                    : "+f"(acc[nf][0]), "+f"(acc[nf][1]), "+f"(acc[nf][2]), "+f"(acc[nf][3])
                    : "r"(a0), "r"(0u), "r"(a2), "r"(0u),
                      "r"(breg[nf][kf][0]), "r"(breg[nf][kf][1]));
            }
        }
#pragma unroll
        for (int kq = 0; kq < KFRAG - KREG; ++kq) {
            const int kf = KREG + kq;
            unsigned a0 = h16s[w * 64 + kf * 8 + tid];
            unsigned a2 = h16s[w * 64 + kf * 8 + 4 + tid];
#pragma unroll
            for (int nf = 0; nf < NFRAG; ++nf) {
                const uint2 bb = *(const uint2*)(wp + (size_t)(((w * NFRAG + nf) * 4 + kq) * 32 + l) * 2);
                asm volatile(
                    "mma.sync.aligned.m16n8k16.row.col.f32.f16.f16.f32 "
                    "{%0,%1,%2,%3},{%4,%5,%6,%7},{%8,%9},{%0,%1,%2,%3};"
                    : "+f"(acc[nf][0]), "+f"(acc[nf][1]), "+f"(acc[nf][2]), "+f"(acc[nf][3])
                    : "r"(a0), "r"(0u), "r"(a2), "r"(0u), "r"(bb.x), "r"(bb.y));
            }
        }
        if (gid == 0) {
#pragma unroll
            for (int nf = 0; nf < NFRAG; ++nf)
                *(float2*)(red + w * 48 + nf * 8 + 2 * tid) = make_float2(acc[nf][0], acc[nf][1]);
        }
        __syncthreads();   // B2

        if (t0 < 48) {
            float s = 0.f;
#pragma unroll
            for (int ww = 0; ww < NWARP; ++ww) s += red[ww * 48 + t0];
            gh[t0] = s;
        }
        __syncthreads();   // B3

        // ---- activation + publish + grid barrier (warp 0 only) ----
        if (w == 0) {
            if (l < PB) {
                float z    = __fdividef(1.f, 1.f + __expf(-(xz + gh[l])));
                float r    = __fdividef(1.f, 1.f + __expf(-(xr + gh[16 + l])));
                float ci   = xn + r * gh[32 + l];
                ci = fminf(fmaxf(ci, -15.f), 15.f);
                float e2   = __expf(2.f * ci);
                float cand = __fdividef(e2 - 1.f, e2 + 1.f);
                float hn   = fmaf(z, cand - hprev, hprev);
                hprev = hn;
                out[(size_t)t * N_DIM + i0 + l] = hn;
                hst[l] = __half_as_ushort(__float2half(hn));
            }
            __syncwarp();
            if (l == 0) {
                uint4 d0 = *(const uint4*)hst;
                uint4 d1 = *((const uint4*)hst + 1);
                uint4* dst = (uint4*)(g_h16[(t + 1) & 1] + i0);
                asm volatile("st.global.v4.u32 [%0], {%1,%2,%3,%4};"
                             :: "l"(dst), "r"(d0.x), "r"(d0.y), "r"(d0.z), "r"(d0.w) : "memory");
                asm volatile("st.global.v4.u32 [%0], {%1,%2,%3,%4};"
                             :: "l"(dst + 1), "r"(d1.x), "r"(d1.y), "r"(d1.z), "r"(d1.w) : "memory");
                if (t < T_SEQ - 1) {
                    unsigned target = (unsigned)(NBLK * (t + 1));
                    asm volatile("red.release.gpu.add.u32 [%0], %1;" :: "l"(&g_ctr), "r"(1u) : "memory");
                    unsigned v;
                    do {
                        asm volatile("ld.acquire.gpu.u32 %0, [%1];" : "=r"(v) : "l"(&g_ctr) : "memory");
                    } while (v < target);
                }
            }
        }
        __syncthreads();   // B4: all blocks' h(t) globally visible
    }
}

// ---------------- launcher ----------------
extern "C" void kernel_launch(void* const* d_in, const int* in_sizes, int n_in,
                              void* d_out, int out_size) {
    const float* x    = (const float*)d_in[0];
    const float* Wx   = (const float*)d_in[1];
    const float* Wh   = (const float*)d_in[2];
    const float* bias = (const float*)d_in[3];
    float* out = (float*)d_out;

    cudaFuncSetAttribute(gru_scan, cudaFuncAttributeMaxDynamicSharedMemorySize, SMEM_SCAN);

    reset_k<<<1, 256>>>();
    conv_x<<<4096, 256>>>(x);
    {
        int n = N_DIM * G_DIM;
        conv_wxt<<<(n + 255) / 256, 256>>>(Wx);
    }
    {
        int n = NBLK * NWARP * NFRAG * KFRAG * 32 * 2;
        pack_wh<<<(n + 255) / 256, 256>>>(Wh);
    }
    gemm_gx<<<dim3(G_DIM / 128, T_SEQ / 128), 256>>>(bias);
    gru_scan<<<NBLK, NTHR, SMEM_SCAN>>>(out);
}

// round 6
// speedup vs baseline: 5.0284x; 1.1717x over previous
#include <cuda_runtime.h>
#include <cuda_fp16.h>
#include <cstdint>

#define N_DIM  2048
#define T_SEQ  8192
#define G_DIM  6144
#define NBLK   128     // persistent blocks (1 per SM, all resident)
#define NTHR   512
#define NWARP  16
#define PB     16      // output elements per block
#define NGATE  3       // z, r, n — each gate = one 16-col A-fragment group
#define KFRAG  8       // k-fragments of 16 per warp (128 k per warp)
#define KREG   4       // kf 0..3 register-resident, kf 4..7 smem-resident

// ---- scratch (device globals: allocation-free rule) ----
__device__ __half        g_x16[(size_t)T_SEQ * N_DIM];          // 32 MB
__device__ __half        g_WxT16[(size_t)G_DIM * N_DIM];        // 25 MB (transposed: [n][k])
__device__ float         g_gx[(size_t)T_SEQ * G_DIM];           // 192 MB
__device__ unsigned int  g_whpack[NBLK * NWARP * NGATE * KFRAG * 32 * 4]; // 25 MB packed A-frags
__device__ __half        g_h16[2][N_DIM];                       // double-buffered h broadcast
__device__ unsigned int  g_ctr;                                 // grid barrier counter

// ---------------- reset ----------------
__global__ void reset_k() {
    if (threadIdx.x == 0) g_ctr = 0u;
    for (int i = threadIdx.x; i < 2 * N_DIM; i += blockDim.x)
        ((__half*)g_h16)[i] = __float2half(0.f);
}

// ---------------- convert x -> fp16 ----------------
__global__ void conv_x(const float* __restrict__ x) {
    const float2* x2 = (const float2*)x;
    __half2* o = (__half2*)g_x16;
    size_t n = (size_t)T_SEQ * N_DIM / 2;
    for (size_t i = blockIdx.x * (size_t)blockDim.x + threadIdx.x; i < n;
         i += (size_t)gridDim.x * blockDim.x)
        o[i] = __float22half2_rn(x2[i]);
}

// ------------- convert+transpose Wx -> WxT fp16 [n][k] -------------
__global__ void conv_wxt(const float* __restrict__ Wx) {
    size_t idx = blockIdx.x * (size_t)blockDim.x + threadIdx.x; // over K*G
    if (idx >= (size_t)N_DIM * G_DIM) return;
    int k = (int)(idx / G_DIM);
    int j = (int)(idx % G_DIM);
    g_WxT16[(size_t)j * N_DIM + k] = __float2half(Wx[idx]);
}

// ------------- pack Wh into per-block mma A fragments (fp16, weights-as-A) -------------
// idx = ((((b*16 + w)*3 + g)*8 + kf)*32 + l)*4 + r
// A is m16n8k16 row-major A-fragment: m = 16 output cols of this (block,gate),
// k = 16-wide k-chunk (kf) of warp w.
//   r0: row gid,   k = 2tid..2tid+1      r1: row gid+8, k = 2tid..2tid+1
//   r2: row gid,   k = 8+2tid..8+2tid+1  r3: row gid+8, k = 8+2tid..
__global__ void pack_wh(const float* __restrict__ Wh) {
    int idx = blockIdx.x * blockDim.x + threadIdx.x;
    if (idx >= NBLK * NWARP * NGATE * KFRAG * 32 * 4) return;
    int r    = idx & 3;
    int l    = (idx >> 2) & 31;
    int kf   = (idx >> 7) & 7;
    int rest = idx >> 10;          // (b*16 + w)*3 + g
    int g    = rest % 3;
    int bw   = rest / 3;
    int w    = bw & 15;
    int b    = bw >> 4;
    int tid  = l & 3, gid = l >> 2;
    int j    = g * N_DIM + b * PB + gid + ((r & 1) ? 8 : 0);   // global Wh column
    int k0   = w * 128 + kf * 16 + ((r & 2) ? 8 : 0) + 2 * tid; // global k
    __half2 h;
    h.x = __float2half(Wh[(size_t)k0 * G_DIM + j]);
    h.y = __float2half(Wh[(size_t)(k0 + 1) * G_DIM + j]);
    g_whpack[idx] = *(unsigned int*)&h;
}

// ---------------- gx = x @ Wx + b  (fp16 mma, fp32 accum) ----------------
__global__ void __launch_bounds__(256) gemm_gx(const float* __restrict__ bias) {
    __shared__ __half As[128 * 40];
    __shared__ __half Bs[128 * 40];
    const int m0 = blockIdx.y * 128, n0 = blockIdx.x * 128;
    const int t = threadIdx.x, w = t >> 5, l = t & 31, tid = l & 3, gid = l >> 2;
    const int wm = w & 3, wn = w >> 2;
    float acc[2][8][4];
#pragma unroll
    for (int mt = 0; mt < 2; ++mt)
#pragma unroll
        for (int nt = 0; nt < 8; ++nt)
#pragma unroll
            for (int q = 0; q < 4; ++q) acc[mt][nt][q] = 0.f;

    for (int kt = 0; kt < N_DIM; kt += 32) {
        {
            int r = t >> 2, c = (t & 3) * 8;
            *(uint4*)(As + r * 40 + c)        = *(const uint4*)(g_x16  + (size_t)(m0 + r)      * N_DIM + kt + c);
            *(uint4*)(As + (r + 64) * 40 + c) = *(const uint4*)(g_x16  + (size_t)(m0 + r + 64) * N_DIM + kt + c);
            *(uint4*)(Bs + r * 40 + c)        = *(const uint4*)(g_WxT16 + (size_t)(n0 + r)      * N_DIM + kt + c);
            *(uint4*)(Bs + (r + 64) * 40 + c) = *(const uint4*)(g_WxT16 + (size_t)(n0 + r + 64) * N_DIM + kt + c);
        }
        __syncthreads();
#pragma unroll
        for (int s = 0; s < 2; ++s) {
            const int ko = s * 16;
            unsigned a[2][4];
#pragma unroll
            for (int mt = 0; mt < 2; ++mt) {
                int rb = wm * 32 + mt * 16;
                a[mt][0] = *(const unsigned*)(As + (rb + gid)     * 40 + ko + 2 * tid);
                a[mt][1] = *(const unsigned*)(As + (rb + gid + 8) * 40 + ko + 2 * tid);
                a[mt][2] = *(const unsigned*)(As + (rb + gid)     * 40 + ko + 2 * tid + 8);
                a[mt][3] = *(const unsigned*)(As + (rb + gid + 8) * 40 + ko + 2 * tid + 8);
            }
#pragma unroll
            for (int nt = 0; nt < 8; ++nt) {
                int cb = wn * 64 + nt * 8 + gid;
                unsigned b0 = *(const unsigned*)(Bs + cb * 40 + ko + 2 * tid);
                unsigned b1 = *(const unsigned*)(Bs + cb * 40 + ko + 2 * tid + 8);
#pragma unroll
                for (int mt = 0; mt < 2; ++mt) {
                    asm volatile(
                        "mma.sync.aligned.m16n8k16.row.col.f32.f16.f16.f32 "
                        "{%0,%1,%2,%3},{%4,%5,%6,%7},{%8,%9},{%0,%1,%2,%3};"
                        : "+f"(acc[mt][nt][0]), "+f"(acc[mt][nt][1]),
                          "+f"(acc[mt][nt][2]), "+f"(acc[mt][nt][3])
                        : "r"(a[mt][0]), "r"(a[mt][1]), "r"(a[mt][2]), "r"(a[mt][3]),
                          "r"(b0), "r"(b1));
                }
            }
        }
        __syncthreads();
    }
#pragma unroll
    for (int mt = 0; mt < 2; ++mt)
#pragma unroll
        for (int nt = 0; nt < 8; ++nt) {
            int row = m0 + wm * 32 + mt * 16 + gid;
            int col = n0 + wn * 64 + nt * 8 + 2 * tid;
            float b0v = __ldg(bias + col), b1v = __ldg(bias + col + 1);
            g_gx[(size_t)row * G_DIM + col]           = acc[mt][nt][0] + b0v;
            g_gx[(size_t)row * G_DIM + col + 1]       = acc[mt][nt][1] + b1v;
            g_gx[(size_t)(row + 8) * G_DIM + col]     = acc[mt][nt][2] + b0v;
            g_gx[(size_t)(row + 8) * G_DIM + col + 1] = acc[mt][nt][3] + b1v;
        }
}

// ---------------- persistent GRU scan (weights-as-A mma, 2 barriers/step) ----------------
// dynamic smem layout (bytes):
//   [0,98304)       packed A-frags, kf 4..7 (24576 u32)
//   [98304,102400)  h16s broadcast (1024 u32; warp-private 256B slices)
//   [102400,105472) red[16][48] f32
//   [105472,105504) hst[16] u16 (publish staging)
#define SMEM_SCAN 105536

__global__ void __launch_bounds__(NTHR, 1) gru_scan(float* __restrict__ out) {
    extern __shared__ unsigned char smem[];
    unsigned int*   wp   = (unsigned int*)smem;                 // kf 4..7 A-frags
    unsigned int*   h16s = (unsigned int*)(smem + 98304);
    float*          red  = (float*)(smem + 102400);
    unsigned short* hst  = (unsigned short*)(smem + 105472);

    const int b  = blockIdx.x;
    const int t0 = threadIdx.x;
    const int w  = t0 >> 5, l = t0 & 31, tid = l & 3, gid = l >> 2;
    const int i0 = b * PB;

    const unsigned* base = g_whpack + (size_t)b * 49152;

    // ---- kf 0..3 A-fragments into registers (persistent, 48 regs) ----
    unsigned breg[NGATE][KREG][4];
#pragma unroll
    for (int g = 0; g < NGATE; ++g)
#pragma unroll
        for (int kf = 0; kf < KREG; ++kf) {
            const uint4 v = *(const uint4*)(base + (size_t)(((w * NGATE + g) * KFRAG + kf) * 32 + l) * 4);
            breg[g][kf][0] = v.x; breg[g][kf][1] = v.y;
            breg[g][kf][2] = v.z; breg[g][kf][3] = v.w;
        }
    // ---- stage kf 4..7 A-fragments into smem (once): frag f=(w*3+g)*4+kq, 128 u32 each ----
    for (int idx = t0; idx < 6144; idx += NTHR) {   // 6144 uint4 = 24576 u32
        int frag   = idx >> 5;       // /32 uint4 per frag
        int within = idx & 31;
        int w3g = frag >> 2, kq = frag & 3;
        ((uint4*)wp)[idx] = *((const uint4*)base + (size_t)((w3g * KFRAG) + 4 + kq) * 32 + within);
    }
    __syncthreads();

    float hprev = 0.f;   // h state, warp 0 lanes 0..15

    for (int t = 0; t < T_SEQ; ++t) {
        // ---- gx prefetch (warp 0; lanes 0-15: xz,xn ; lanes 16-31: xr) ----
        float xa = 0.f, xb = 0.f;
        if (w == 0) {
            const float* gxr = g_gx + (size_t)t * G_DIM + i0;
            if (l < 16) { xa = __ldg(gxr + l); xb = __ldg(gxr + 2 * N_DIM + l); }
            else        { xa = __ldg(gxr + N_DIM + l - 16); }
        }
        // ---- h broadcast: each warp fills ONLY its own 256B slice -> syncwarp suffices ----
        {
            const uint2* hg = (const uint2*)(g_h16[t & 1]);
            unsigned v0, v1;
            asm volatile("ld.global.cg.v2.u32 {%0,%1}, [%2];"
                         : "=r"(v0), "=r"(v1) : "l"(hg + t0));
            ((uint2*)h16s)[t0] = make_uint2(v0, v1);
        }
        __syncwarp();

        // ---- mma: 3 gates x 8 kfrags; A = weights (16 cols), B = h replicated ----
        float acc[NGATE][4];
#pragma unroll
        for (int g = 0; g < NGATE; ++g)
#pragma unroll
            for (int q = 0; q < 4; ++q) acc[g][q] = 0.f;

#pragma unroll
        for (int kf = 0; kf < KREG; ++kf) {
            unsigned b0 = h16s[w * 64 + kf * 8 + tid];
            unsigned b1 = h16s[w * 64 + kf * 8 + 4 + tid];
#pragma unroll
            for (int g = 0; g < NGATE; ++g) {
                asm volatile(
                    "mma.sync.aligned.m16n8k16.row.col.f32.f16.f16.f32 "
                    "{%0,%1,%2,%3},{%4,%5,%6,%7},{%8,%9},{%0,%1,%2,%3};"
                    : "+f"(acc[g][0]), "+f"(acc[g][1]), "+f"(acc[g][2]), "+f"(acc[g][3])
                    : "r"(breg[g][kf][0]), "r"(breg[g][kf][1]),
                      "r"(breg[g][kf][2]), "r"(breg[g][kf][3]),
                      "r"(b0), "r"(b1));
            }
        }
#pragma unroll
        for (int kq = 0; kq < KFRAG - KREG; ++kq) {
            const int kf = KREG + kq;
            unsigned b0 = h16s[w * 64 + kf * 8 + tid];
            unsigned b1 = h16s[w * 64 + kf * 8 + 4 + tid];
#pragma unroll
            for (int g = 0; g < NGATE; ++g) {
                const uint4 av = *(const uint4*)(wp + (size_t)(((w * NGATE + g) * 4 + kq) * 32 + l) * 4);
                asm volatile(
                    "mma.sync.aligned.m16n8k16.row.col.f32.f16.f16.f32 "
                    "{%0,%1,%2,%3},{%4,%5,%6,%7},{%8,%9},{%0,%1,%2,%3};"
                    : "+f"(acc[g][0]), "+f"(acc[g][1]), "+f"(acc[g][2]), "+f"(acc[g][3])
                    : "r"(av.x), "r"(av.y), "r"(av.z), "r"(av.w), "r"(b0), "r"(b1));
            }
        }
        // ---- partials: n=0 column lives in lanes tid==0 (c0 row gid, c2 row gid+8) ----
        if (tid == 0) {
#pragma unroll
            for (int g = 0; g < NGATE; ++g) {
                red[w * 48 + g * 16 + gid]     = acc[g][0];
                red[w * 48 + g * 16 + gid + 8] = acc[g][2];
            }
        }
        __syncthreads();   // B2: partials visible to warp 0

        // ---- reduce + activation + publish + grid barrier (warp 0 only) ----
        if (w == 0) {
            float sa = 0.f, sb = 0.f;
#pragma unroll
            for (int ww = 0; ww < NWARP; ++ww) {
                sa += red[ww * 48 + l];                       // l<16: z, l>=16: r
                sb += red[ww * 48 + 32 + (l & 15)];           // n (used by lanes <16)
            }
            float sig = __fdividef(1.f, 1.f + __expf(-(xa + sa)));  // low: z, high: r
            float r   = __shfl_sync(0xffffffffu, sig, (l + 16) & 31);
            float ci  = xb + r * sb;
            ci = fminf(fmaxf(ci, -15.f), 15.f);
            float e2  = __expf(2.f * ci);
            float cand = __fdividef(e2 - 1.f, e2 + 1.f);
            if (l < 16) {
                float hn = fmaf(sig, cand - hprev, hprev);
                hprev = hn;
                out[(size_t)t * N_DIM + i0 + l] = hn;
                hst[l] = __half_as_ushort(__float2half(hn));
            }
            __syncwarp();
            if (l == 0) {
                uint4 d0 = *(const uint4*)hst;
                uint4 d1 = *((const uint4*)hst + 1);
                uint4* dst = (uint4*)(g_h16[(t + 1) & 1] + i0);
                asm volatile("st.global.v4.u32 [%0], {%1,%2,%3,%4};"
                             :: "l"(dst), "r"(d0.x), "r"(d0.y), "r"(d0.z), "r"(d0.w) : "memory");
                asm volatile("st.global.v4.u32 [%0], {%1,%2,%3,%4};"
                             :: "l"(dst + 1), "r"(d1.x), "r"(d1.y), "r"(d1.z), "r"(d1.w) : "memory");
                if (t < T_SEQ - 1) {
                    unsigned target = (unsigned)(NBLK * (t + 1));
                    asm volatile("red.release.gpu.add.u32 [%0], %1;" :: "l"(&g_ctr), "r"(1u) : "memory");
                    unsigned v;
                    do {
                        asm volatile("ld.acquire.gpu.u32 %0, [%1];" : "=r"(v) : "l"(&g_ctr) : "memory");
                    } while (v < target);
                }
            }
        }
        __syncthreads();   // B4: all blocks' h(t) globally visible
    }
}

// ---------------- launcher ----------------
extern "C" void kernel_launch(void* const* d_in, const int* in_sizes, int n_in,
                              void* d_out, int out_size) {
    const float* x    = (const float*)d_in[0];
    const float* Wx   = (const float*)d_in[1];
    const float* Wh   = (const float*)d_in[2];
    const float* bias = (const float*)d_in[3];
    float* out = (float*)d_out;

    cudaFuncSetAttribute(gru_scan, cudaFuncAttributeMaxDynamicSharedMemorySize, SMEM_SCAN);

    reset_k<<<1, 256>>>();
    conv_x<<<4096, 256>>>(x);
    {
        int n = N_DIM * G_DIM;
        conv_wxt<<<(n + 255) / 256, 256>>>(Wx);
    }
    {
        int n = NBLK * NWARP * NGATE * KFRAG * 32 * 4;
        pack_wh<<<(n + 255) / 256, 256>>>(Wh);
    }
    gemm_gx<<<dim3(G_DIM / 128, T_SEQ / 128), 256>>>(bias);
    gru_scan<<<NBLK, NTHR, SMEM_SCAN>>>(out);
}

// round 7
// speedup vs baseline: 5.0940x; 1.0130x over previous
#include <cuda_runtime.h>
#include <cuda_fp16.h>
#include <cstdint>

#define N_DIM  2048
#define T_SEQ  8192
#define G_DIM  6144
#define NBLK   128     // persistent blocks (1 per SM, all resident)
#define NTHR   512
#define NWARP  16
#define PB     16      // output elements per block
#define NGATE  3       // z, r, n — each gate = one 16-col A-fragment group
#define KFRAG  8       // k-fragments of 16 per warp (128 k per warp)

// ---- scratch (device globals: allocation-free rule) ----
__device__ __half        g_x16[(size_t)T_SEQ * N_DIM];          // 32 MB
__device__ __half        g_WxT16[(size_t)G_DIM * N_DIM];        // 25 MB (transposed: [n][k])
__device__ float         g_gx[(size_t)T_SEQ * G_DIM];           // 192 MB
__device__ unsigned int  g_whpack[NBLK * NWARP * NGATE * KFRAG * 32 * 4]; // 25 MB packed A-frags
__device__ __half        g_h16[2][N_DIM];                       // double-buffered h broadcast
__device__ unsigned int  g_ctr;                                 // grid barrier counter

// ---------------- reset ----------------
__global__ void reset_k() {
    if (threadIdx.x == 0) g_ctr = 0u;
    for (int i = threadIdx.x; i < 2 * N_DIM; i += blockDim.x)
        ((__half*)g_h16)[i] = __float2half(0.f);
}

// ---------------- convert x -> fp16 ----------------
__global__ void conv_x(const float* __restrict__ x) {
    const float2* x2 = (const float2*)x;
    __half2* o = (__half2*)g_x16;
    size_t n = (size_t)T_SEQ * N_DIM / 2;
    for (size_t i = blockIdx.x * (size_t)blockDim.x + threadIdx.x; i < n;
         i += (size_t)gridDim.x * blockDim.x)
        o[i] = __float22half2_rn(x2[i]);
}

// ------------- convert+transpose Wx -> WxT fp16 [n][k] -------------
__global__ void conv_wxt(const float* __restrict__ Wx) {
    size_t idx = blockIdx.x * (size_t)blockDim.x + threadIdx.x; // over K*G
    if (idx >= (size_t)N_DIM * G_DIM) return;
    int k = (int)(idx / G_DIM);
    int j = (int)(idx % G_DIM);
    g_WxT16[(size_t)j * N_DIM + k] = __float2half(Wx[idx]);
}

// ------------- pack Wh into per-block mma A fragments (fp16, weights-as-A) -------------
// idx = ((((b*16 + w)*3 + g)*8 + kf)*32 + l)*4 + r
//   r0: row gid,   k = 2tid..2tid+1      r1: row gid+8, k = 2tid..2tid+1
//   r2: row gid,   k = 8+2tid..          r3: row gid+8, k = 8+2tid..
__global__ void pack_wh(const float* __restrict__ Wh) {
    int idx = blockIdx.x * blockDim.x + threadIdx.x;
    if (idx >= NBLK * NWARP * NGATE * KFRAG * 32 * 4) return;
    int r    = idx & 3;
    int l    = (idx >> 2) & 31;
    int kf   = (idx >> 7) & 7;
    int rest = idx >> 10;          // (b*16 + w)*3 + g
    int g    = rest % 3;
    int bw   = rest / 3;
    int w    = bw & 15;
    int b    = bw >> 4;
    int tid  = l & 3, gid = l >> 2;
    int j    = g * N_DIM + b * PB + gid + ((r & 1) ? 8 : 0);   // global Wh column
    int k0   = w * 128 + kf * 16 + ((r & 2) ? 8 : 0) + 2 * tid; // global k
    __half2 h;
    h.x = __float2half(Wh[(size_t)k0 * G_DIM + j]);
    h.y = __float2half(Wh[(size_t)(k0 + 1) * G_DIM + j]);
    g_whpack[idx] = *(unsigned int*)&h;
}

// ---------------- gx = x @ Wx + b  (fp16 mma, fp32 accum) ----------------
__global__ void __launch_bounds__(256) gemm_gx(const float* __restrict__ bias) {
    __shared__ __half As[128 * 40];
    __shared__ __half Bs[128 * 40];
    const int m0 = blockIdx.y * 128, n0 = blockIdx.x * 128;
    const int t = threadIdx.x, w = t >> 5, l = t & 31, tid = l & 3, gid = l >> 2;
    const int wm = w & 3, wn = w >> 2;
    float acc[2][8][4];
#pragma unroll
    for (int mt = 0; mt < 2; ++mt)
#pragma unroll
        for (int nt = 0; nt < 8; ++nt)
#pragma unroll
            for (int q = 0; q < 4; ++q) acc[mt][nt][q] = 0.f;

    for (int kt = 0; kt < N_DIM; kt += 32) {
        {
            int r = t >> 2, c = (t & 3) * 8;
            *(uint4*)(As + r * 40 + c)        = *(const uint4*)(g_x16  + (size_t)(m0 + r)      * N_DIM + kt + c);
            *(uint4*)(As + (r + 64) * 40 + c) = *(const uint4*)(g_x16  + (size_t)(m0 + r + 64) * N_DIM + kt + c);
            *(uint4*)(Bs + r * 40 + c)        = *(const uint4*)(g_WxT16 + (size_t)(n0 + r)      * N_DIM + kt + c);
            *(uint4*)(Bs + (r + 64) * 40 + c) = *(const uint4*)(g_WxT16 + (size_t)(n0 + r + 64) * N_DIM + kt + c);
        }
        __syncthreads();
#pragma unroll
        for (int s = 0; s < 2; ++s) {
            const int ko = s * 16;
            unsigned a[2][4];
#pragma unroll
            for (int mt = 0; mt < 2; ++mt) {
                int rb = wm * 32 + mt * 16;
                a[mt][0] = *(const unsigned*)(As + (rb + gid)     * 40 + ko + 2 * tid);
                a[mt][1] = *(const unsigned*)(As + (rb + gid + 8) * 40 + ko + 2 * tid);
                a[mt][2] = *(const unsigned*)(As + (rb + gid)     * 40 + ko + 2 * tid + 8);
                a[mt][3] = *(const unsigned*)(As + (rb + gid + 8) * 40 + ko + 2 * tid + 8);
            }
#pragma unroll
            for (int nt = 0; nt < 8; ++nt) {
                int cb = wn * 64 + nt * 8 + gid;
                unsigned b0 = *(const unsigned*)(Bs + cb * 40 + ko + 2 * tid);
                unsigned b1 = *(const unsigned*)(Bs + cb * 40 + ko + 2 * tid + 8);
#pragma unroll
                for (int mt = 0; mt < 2; ++mt) {
                    asm volatile(
                        "mma.sync.aligned.m16n8k16.row.col.f32.f16.f16.f32 "
                        "{%0,%1,%2,%3},{%4,%5,%6,%7},{%8,%9},{%0,%1,%2,%3};"
                        : "+f"(acc[mt][nt][0]), "+f"(acc[mt][nt][1]),
                          "+f"(acc[mt][nt][2]), "+f"(acc[mt][nt][3])
                        : "r"(a[mt][0]), "r"(a[mt][1]), "r"(a[mt][2]), "r"(a[mt][3]),
                          "r"(b0), "r"(b1));
                }
            }
        }
        __syncthreads();
    }
#pragma unroll
    for (int mt = 0; mt < 2; ++mt)
#pragma unroll
        for (int nt = 0; nt < 8; ++nt) {
            int row = m0 + wm * 32 + mt * 16 + gid;
            int col = n0 + wn * 64 + nt * 8 + 2 * tid;
            float b0v = __ldg(bias + col), b1v = __ldg(bias + col + 1);
            g_gx[(size_t)row * G_DIM + col]           = acc[mt][nt][0] + b0v;
            g_gx[(size_t)row * G_DIM + col + 1]       = acc[mt][nt][1] + b1v;
            g_gx[(size_t)(row + 8) * G_DIM + col]     = acc[mt][nt][2] + b0v;
            g_gx[(size_t)(row + 8) * G_DIM + col + 1] = acc[mt][nt][3] + b1v;
        }
}

// ---------------- persistent GRU scan (full register-resident weights) ----------------
// dynamic smem layout (bytes):
//   [0,4096)     h16s broadcast (1024 u32; warp-private 256B slices)
//   [4096,7168)  red[16][48] f32
//   [7168,7200)  hst[16] u16 (publish staging)
#define SMEM_SCAN 7232

__global__ void __launch_bounds__(NTHR, 1) gru_scan(float* __restrict__ out) {
    extern __shared__ unsigned char smem[];
    unsigned int*   h16s = (unsigned int*)smem;
    float*          red  = (float*)(smem + 4096);
    unsigned short* hst  = (unsigned short*)(smem + 7168);

    const int b  = blockIdx.x;
    const int t0 = threadIdx.x;
    const int w  = t0 >> 5, l = t0 & 31, tid = l & 3, gid = l >> 2;
    const int i0 = b * PB;

    const unsigned* base = g_whpack + (size_t)b * 49152;

    // ---- ALL 8 kf A-fragments into registers (persistent, 96 regs) ----
    unsigned breg[NGATE][KFRAG][4];
#pragma unroll
    for (int g = 0; g < NGATE; ++g)
#pragma unroll
        for (int kf = 0; kf < KFRAG; ++kf) {
            const uint4 v = *(const uint4*)(base + (size_t)(((w * NGATE + g) * KFRAG + kf) * 32 + l) * 4);
            breg[g][kf][0] = v.x; breg[g][kf][1] = v.y;
            breg[g][kf][2] = v.z; breg[g][kf][3] = v.w;
        }
    __syncthreads();

    float hprev = 0.f;   // h state, warp 0 lanes 0..15

    for (int t = 0; t < T_SEQ; ++t) {
        // ---- gx prefetch (warp 0; lanes 0-15: xz,xn ; lanes 16-31: xr) ----
        float xa = 0.f, xb = 0.f;
        if (w == 0) {
            const float* gxr = g_gx + (size_t)t * G_DIM + i0;
            if (l < 16) { xa = __ldg(gxr + l); xb = __ldg(gxr + 2 * N_DIM + l); }
            else        { xa = __ldg(gxr + N_DIM + l - 16); }
        }
        // ---- h broadcast: each warp fills ONLY its own 256B slice -> syncwarp suffices ----
        {
            const uint2* hg = (const uint2*)(g_h16[t & 1]);
            unsigned v0, v1;
            asm volatile("ld.global.cg.v2.u32 {%0,%1}, [%2];"
                         : "=r"(v0), "=r"(v1) : "l"(hg + t0));
            ((uint2*)h16s)[t0] = make_uint2(v0, v1);
        }
        __syncwarp();

        // ---- mma: 3 gates x 8 kfrags; A = weights (regs), B = h replicated ----
        float acc[NGATE][4];
#pragma unroll
        for (int g = 0; g < NGATE; ++g)
#pragma unroll
            for (int q = 0; q < 4; ++q) acc[g][q] = 0.f;

#pragma unroll
        for (int kf = 0; kf < KFRAG; ++kf) {
            unsigned b0 = h16s[w * 64 + kf * 8 + tid];
            unsigned b1 = h16s[w * 64 + kf * 8 + 4 + tid];
#pragma unroll
            for (int g = 0; g < NGATE; ++g) {
                asm volatile(
                    "mma.sync.aligned.m16n8k16.row.col.f32.f16.f16.f32 "
                    "{%0,%1,%2,%3},{%4,%5,%6,%7},{%8,%9},{%0,%1,%2,%3};"
                    : "+f"(acc[g][0]), "+f"(acc[g][1]), "+f"(acc[g][2]), "+f"(acc[g][3])
                    : "r"(breg[g][kf][0]), "r"(breg[g][kf][1]),
                      "r"(breg[g][kf][2]), "r"(breg[g][kf][3]),
                      "r"(b0), "r"(b1));
            }
        }
        // ---- partials: n=0 column lives in lanes tid==0 (c0 row gid, c2 row gid+8) ----
        if (tid == 0) {
#pragma unroll
            for (int g = 0; g < NGATE; ++g) {
                red[w * 48 + g * 16 + gid]     = acc[g][0];
                red[w * 48 + g * 16 + gid + 8] = acc[g][2];
            }
        }
        __syncthreads();   // B2: partials visible to warp 0

        // ---- reduce + activation + publish + grid barrier (warp 0 only) ----
        if (w == 0) {
            float sa = 0.f, sb = 0.f;
#pragma unroll
            for (int ww = 0; ww < NWARP; ++ww) {
                sa += red[ww * 48 + l];                       // l<16: z, l>=16: r
                sb += red[ww * 48 + 32 + (l & 15)];           // n (used by lanes <16)
            }
            float sig = __fdividef(1.f, 1.f + __expf(-(xa + sa)));  // low: z, high: r
            float r   = __shfl_sync(0xffffffffu, sig, (l + 16) & 31);
            float ci  = xb + r * sb;
            ci = fminf(fmaxf(ci, -15.f), 15.f);
            float e2  = __expf(2.f * ci);
            float cand = __fdividef(e2 - 1.f, e2 + 1.f);
            if (l < 16) {
                float hn = fmaf(sig, cand - hprev, hprev);
                hprev = hn;
                out[(size_t)t * N_DIM + i0 + l] = hn;
                hst[l] = __half_as_ushort(__float2half(hn));
            }
            __syncwarp();
            if (l == 0) {
                uint4 d0 = *(const uint4*)hst;
                uint4 d1 = *((const uint4*)hst + 1);
                uint4* dst = (uint4*)(g_h16[(t + 1) & 1] + i0);
                asm volatile("st.global.v4.u32 [%0], {%1,%2,%3,%4};"
                             :: "l"(dst), "r"(d0.x), "r"(d0.y), "r"(d0.z), "r"(d0.w) : "memory");
                asm volatile("st.global.v4.u32 [%0], {%1,%2,%3,%4};"
                             :: "l"(dst + 1), "r"(d1.x), "r"(d1.y), "r"(d1.z), "r"(d1.w) : "memory");
                if (t < T_SEQ - 1) {
                    unsigned target = (unsigned)(NBLK * (t + 1));
                    asm volatile("red.release.gpu.add.u32 [%0], %1;" :: "l"(&g_ctr), "r"(1u) : "memory");
                    unsigned v;
                    do {
                        asm volatile("ld.acquire.gpu.u32 %0, [%1];" : "=r"(v) : "l"(&g_ctr) : "memory");
                    } while (v < target);
                }
            }
        }
        __syncthreads();   // B4: all blocks' h(t) globally visible
    }
}

// ---------------- launcher ----------------
extern "C" void kernel_launch(void* const* d_in, const int* in_sizes, int n_in,
                              void* d_out, int out_size) {
    const float* x    = (const float*)d_in[0];
    const float* Wx   = (const float*)d_in[1];
    const float* Wh   = (const float*)d_in[2];
    const float* bias = (const float*)d_in[3];
    float* out = (float*)d_out;

    cudaFuncSetAttribute(gru_scan, cudaFuncAttributeMaxDynamicSharedMemorySize, SMEM_SCAN);

    reset_k<<<1, 256>>>();
    conv_x<<<4096, 256>>>(x);
    {
        int n = N_DIM * G_DIM;
        conv_wxt<<<(n + 255) / 256, 256>>>(Wx);
    }
    {
        int n = NBLK * NWARP * NGATE * KFRAG * 32 * 4;
        pack_wh<<<(n + 255) / 256, 256>>>(Wh);
    }
    gemm_gx<<<dim3(G_DIM / 128, T_SEQ / 128), 256>>>(bias);
    gru_scan<<<NBLK, NTHR, SMEM_SCAN>>>(out);
}

// round 8
// speedup vs baseline: 5.1687x; 1.0147x over previous
#include <cuda_runtime.h>
#include <cuda_fp16.h>
#include <cstdint>

#define N_DIM  2048
#define T_SEQ  8192
#define G_DIM  6144
#define NBLK   128     // persistent blocks (1 per SM, all resident)
#define NTHR   512
#define NWARP  16
#define PB     16      // output elements per block
#define NGATE  3       // z, r, n — each gate = one 16-col A-fragment group
#define KFRAG  8       // k-fragments of 16 per warp (128 k per warp)

// ---- scratch (device globals: allocation-free rule) ----
__device__ __half        g_x16[(size_t)T_SEQ * N_DIM];          // 32 MB
__device__ __half        g_WxT16[(size_t)G_DIM * N_DIM];        // 25 MB (transposed: [n][k])
__device__ float         g_gx[(size_t)T_SEQ * G_DIM];           // 192 MB
__device__ unsigned int  g_whpack[NBLK * NWARP * NGATE * KFRAG * 32 * 4]; // 25 MB packed A-frags
__device__ __half        g_h16[2][N_DIM];                       // double-buffered h broadcast
__device__ unsigned int  g_ctr;                                 // grid barrier counter

// ---------------- reset ----------------
__global__ void reset_k() {
    if (threadIdx.x == 0) g_ctr = 0u;
    for (int i = threadIdx.x; i < 2 * N_DIM; i += blockDim.x)
        ((__half*)g_h16)[i] = __float2half(0.f);
}

// ---------------- convert x -> fp16 ----------------
__global__ void conv_x(const float* __restrict__ x) {
    const float2* x2 = (const float2*)x;
    __half2* o = (__half2*)g_x16;
    size_t n = (size_t)T_SEQ * N_DIM / 2;
    for (size_t i = blockIdx.x * (size_t)blockDim.x + threadIdx.x; i < n;
         i += (size_t)gridDim.x * blockDim.x)
        o[i] = __float22half2_rn(x2[i]);
}

// ------------- convert+transpose Wx -> WxT fp16 [n][k] -------------
__global__ void conv_wxt(const float* __restrict__ Wx) {
    size_t idx = blockIdx.x * (size_t)blockDim.x + threadIdx.x; // over K*G
    if (idx >= (size_t)N_DIM * G_DIM) return;
    int k = (int)(idx / G_DIM);
    int j = (int)(idx % G_DIM);
    g_WxT16[(size_t)j * N_DIM + k] = __float2half(Wx[idx]);
}

// ------------- pack Wh into per-block mma A fragments (fp16, weights-as-A) -------------
// idx = ((((b*16 + w)*3 + g)*8 + kf)*32 + l)*4 + r
//   r0: row gid,   k = 2tid..2tid+1      r1: row gid+8, k = 2tid..2tid+1
//   r2: row gid,   k = 8+2tid..          r3: row gid+8, k = 8+2tid..
__global__ void pack_wh(const float* __restrict__ Wh) {
    int idx = blockIdx.x * blockDim.x + threadIdx.x;
    if (idx >= NBLK * NWARP * NGATE * KFRAG * 32 * 4) return;
    int r    = idx & 3;
    int l    = (idx >> 2) & 31;
    int kf   = (idx >> 7) & 7;
    int rest = idx >> 10;          // (b*16 + w)*3 + g
    int g    = rest % 3;
    int bw   = rest / 3;
    int w    = bw & 15;
    int b    = bw >> 4;
    int tid  = l & 3, gid = l >> 2;
    int j    = g * N_DIM + b * PB + gid + ((r & 1) ? 8 : 0);   // global Wh column
    int k0   = w * 128 + kf * 16 + ((r & 2) ? 8 : 0) + 2 * tid; // global k
    __half2 h;
    h.x = __float2half(Wh[(size_t)k0 * G_DIM + j]);
    h.y = __float2half(Wh[(size_t)(k0 + 1) * G_DIM + j]);
    g_whpack[idx] = *(unsigned int*)&h;
}

// ---------------- gx = x @ Wx + b  (fp16 mma, fp32 accum) ----------------
__global__ void __launch_bounds__(256) gemm_gx(const float* __restrict__ bias) {
    __shared__ __half As[128 * 40];
    __shared__ __half Bs[128 * 40];
    const int m0 = blockIdx.y * 128, n0 = blockIdx.x * 128;
    const int t = threadIdx.x, w = t >> 5, l = t & 31, tid = l & 3, gid = l >> 2;
    const int wm = w & 3, wn = w >> 2;
    float acc[2][8][4];
#pragma unroll
    for (int mt = 0; mt < 2; ++mt)
#pragma unroll
        for (int nt = 0; nt < 8; ++nt)
#pragma unroll
            for (int q = 0; q < 4; ++q) acc[mt][nt][q] = 0.f;

    for (int kt = 0; kt < N_DIM; kt += 32) {
        {
            int r = t >> 2, c = (t & 3) * 8;
            *(uint4*)(As + r * 40 + c)        = *(const uint4*)(g_x16  + (size_t)(m0 + r)      * N_DIM + kt + c);
            *(uint4*)(As + (r + 64) * 40 + c) = *(const uint4*)(g_x16  + (size_t)(m0 + r + 64) * N_DIM + kt + c);
            *(uint4*)(Bs + r * 40 + c)        = *(const uint4*)(g_WxT16 + (size_t)(n0 + r)      * N_DIM + kt + c);
            *(uint4*)(Bs + (r + 64) * 40 + c) = *(const uint4*)(g_WxT16 + (size_t)(n0 + r + 64) * N_DIM + kt + c);
        }
        __syncthreads();
#pragma unroll
        for (int s = 0; s < 2; ++s) {
            const int ko = s * 16;
            unsigned a[2][4];
#pragma unroll
            for (int mt = 0; mt < 2; ++mt) {
                int rb = wm * 32 + mt * 16;
                a[mt][0] = *(const unsigned*)(As + (rb + gid)     * 40 + ko + 2 * tid);
                a[mt][1] = *(const unsigned*)(As + (rb + gid + 8) * 40 + ko + 2 * tid);
                a[mt][2] = *(const unsigned*)(As + (rb + gid)     * 40 + ko + 2 * tid + 8);
                a[mt][3] = *(const unsigned*)(As + (rb + gid + 8) * 40 + ko + 2 * tid + 8);
            }
#pragma unroll
            for (int nt = 0; nt < 8; ++nt) {
                int cb = wn * 64 + nt * 8 + gid;
                unsigned b0 = *(const unsigned*)(Bs + cb * 40 + ko + 2 * tid);
                unsigned b1 = *(const unsigned*)(Bs + cb * 40 + ko + 2 * tid + 8);
#pragma unroll
                for (int mt = 0; mt < 2; ++mt) {
                    asm volatile(
                        "mma.sync.aligned.m16n8k16.row.col.f32.f16.f16.f32 "
                        "{%0,%1,%2,%3},{%4,%5,%6,%7},{%8,%9},{%0,%1,%2,%3};"
                        : "+f"(acc[mt][nt][0]), "+f"(acc[mt][nt][1]),
                          "+f"(acc[mt][nt][2]), "+f"(acc[mt][nt][3])
                        : "r"(a[mt][0]), "r"(a[mt][1]), "r"(a[mt][2]), "r"(a[mt][3]),
                          "r"(b0), "r"(b1));
                }
            }
        }
        __syncthreads();
    }
#pragma unroll
    for (int mt = 0; mt < 2; ++mt)
#pragma unroll
        for (int nt = 0; nt < 8; ++nt) {
            int row = m0 + wm * 32 + mt * 16 + gid;
            int col = n0 + wn * 64 + nt * 8 + 2 * tid;
            float b0v = __ldg(bias + col), b1v = __ldg(bias + col + 1);
            g_gx[(size_t)row * G_DIM + col]           = acc[mt][nt][0] + b0v;
            g_gx[(size_t)row * G_DIM + col + 1]       = acc[mt][nt][1] + b1v;
            g_gx[(size_t)(row + 8) * G_DIM + col]     = acc[mt][nt][2] + b0v;
            g_gx[(size_t)(row + 8) * G_DIM + col + 1] = acc[mt][nt][3] + b1v;
        }
}

// ---------------- persistent GRU scan (reg-resident weights + gx prefetch-ahead) ----------------
// dynamic smem layout (bytes):
//   [0,4096)     h16s broadcast (1024 u32; warp-private 256B slices)
//   [4096,7168)  red[16][48] f32
//   [7168,7200)  hst[16] u16 (publish staging)
#define SMEM_SCAN 7232

__global__ void __launch_bounds__(NTHR, 1) gru_scan(float* __restrict__ out) {
    extern __shared__ unsigned char smem[];
    unsigned int*   h16s = (unsigned int*)smem;
    float*          red  = (float*)(smem + 4096);
    unsigned short* hst  = (unsigned short*)(smem + 7168);

    const int b  = blockIdx.x;
    const int t0 = threadIdx.x;
    const int w  = t0 >> 5, l = t0 & 31, tid = l & 3, gid = l >> 2;
    const int i0 = b * PB;

    const unsigned* base = g_whpack + (size_t)b * 49152;

    // ---- ALL 8 kf A-fragments into registers (persistent, 96 regs) ----
    unsigned breg[NGATE][KFRAG][4];
#pragma unroll
    for (int g = 0; g < NGATE; ++g)
#pragma unroll
        for (int kf = 0; kf < KFRAG; ++kf) {
            const uint4 v = *(const uint4*)(base + (size_t)(((w * NGATE + g) * KFRAG + kf) * 32 + l) * 4);
            breg[g][kf][0] = v.x; breg[g][kf][1] = v.y;
            breg[g][kf][2] = v.z; breg[g][kf][3] = v.w;
        }
    __syncthreads();

    // prime the gx prefetch for t=0
    if (w == 0 && l < 3) {
        const float* p = g_gx + (size_t)l * N_DIM + i0;
        asm volatile("prefetch.global.L1 [%0];" :: "l"(p));
    }

    float hprev = 0.f;   // h state, warp 0 lanes 0..15

    for (int t = 0; t < T_SEQ; ++t) {
        // ---- prefetch NEXT step's gx lines (zero-register; full step of slack) ----
        if (w == 0 && l < 3 && t + 1 < T_SEQ) {
            const float* p = g_gx + (size_t)(t + 1) * G_DIM + (size_t)l * N_DIM + i0;
            asm volatile("prefetch.global.L1 [%0];" :: "l"(p));
        }
        // ---- gx load for THIS step (L1-hit thanks to last step's prefetch) ----
        float xa = 0.f, xb = 0.f;
        if (w == 0) {
            const float* gxr = g_gx + (size_t)t * G_DIM + i0;
            if (l < 16) { xa = __ldg(gxr + l); xb = __ldg(gxr + 2 * N_DIM + l); }
            else        { xa = __ldg(gxr + N_DIM + l - 16); }
        }
        // ---- h broadcast: each warp fills ONLY its own 256B slice -> syncwarp suffices ----
        {
            const uint2* hg = (const uint2*)(g_h16[t & 1]);
            unsigned v0, v1;
            asm volatile("ld.global.cg.v2.u32 {%0,%1}, [%2];"
                         : "=r"(v0), "=r"(v1) : "l"(hg + t0));
            ((uint2*)h16s)[t0] = make_uint2(v0, v1);
        }
        __syncwarp();

        // ---- mma: 3 gates x 8 kfrags; A = weights (regs), B = h replicated ----
        float acc[NGATE][4];
#pragma unroll
        for (int g = 0; g < NGATE; ++g)
#pragma unroll
            for (int q = 0; q < 4; ++q) acc[g][q] = 0.f;

#pragma unroll
        for (int kf = 0; kf < KFRAG; ++kf) {
            unsigned b0 = h16s[w * 64 + kf * 8 + tid];
            unsigned b1 = h16s[w * 64 + kf * 8 + 4 + tid];
#pragma unroll
            for (int g = 0; g < NGATE; ++g) {
                asm volatile(
                    "mma.sync.aligned.m16n8k16.row.col.f32.f16.f16.f32 "
                    "{%0,%1,%2,%3},{%4,%5,%6,%7},{%8,%9},{%0,%1,%2,%3};"
                    : "+f"(acc[g][0]), "+f"(acc[g][1]), "+f"(acc[g][2]), "+f"(acc[g][3])
                    : "r"(breg[g][kf][0]), "r"(breg[g][kf][1]),
                      "r"(breg[g][kf][2]), "r"(breg[g][kf][3]),
                      "r"(b0), "r"(b1));
            }
        }
        // ---- partials: n=0 column lives in lanes tid==0 (c0 row gid, c2 row gid+8) ----
        if (tid == 0) {
#pragma unroll
            for (int g = 0; g < NGATE; ++g) {
                red[w * 48 + g * 16 + gid]     = acc[g][0];
                red[w * 48 + g * 16 + gid + 8] = acc[g][2];
            }
        }
        __syncthreads();   // B2: partials visible to warp 0

        // ---- reduce + activation + publish + grid barrier (warp 0 only) ----
        if (w == 0) {
            float sa = 0.f, sb = 0.f;
#pragma unroll
            for (int ww = 0; ww < NWARP; ++ww) {
                sa += red[ww * 48 + l];                       // l<16: z, l>=16: r
                sb += red[ww * 48 + 32 + (l & 15)];           // n (used by lanes <16)
            }
            float sig = __fdividef(1.f, 1.f + __expf(-(xa + sa)));  // low: z, high: r
            float r   = __shfl_sync(0xffffffffu, sig, (l + 16) & 31);
            float ci  = xb + r * sb;
            ci = fminf(fmaxf(ci, -15.f), 15.f);
            float e2  = __expf(2.f * ci);
            float cand = __fdividef(e2 - 1.f, e2 + 1.f);
            if (l < 16) {
                float hn = fmaf(sig, cand - hprev, hprev);
                hprev = hn;
                out[(size_t)t * N_DIM + i0 + l] = hn;
                hst[l] = __half_as_ushort(__float2half(hn));
            }
            __syncwarp();
            if (l == 0) {
                uint4 d0 = *(const uint4*)hst;
                uint4 d1 = *((const uint4*)hst + 1);
                uint4* dst = (uint4*)(g_h16[(t + 1) & 1] + i0);
                asm volatile("st.global.v4.u32 [%0], {%1,%2,%3,%4};"
                             :: "l"(dst), "r"(d0.x), "r"(d0.y), "r"(d0.z), "r"(d0.w) : "memory");
                asm volatile("st.global.v4.u32 [%0], {%1,%2,%3,%4};"
                             :: "l"(dst + 1), "r"(d1.x), "r"(d1.y), "r"(d1.z), "r"(d1.w) : "memory");
                if (t < T_SEQ - 1) {
                    unsigned target = (unsigned)(NBLK * (t + 1));
                    asm volatile("red.release.gpu.add.u32 [%0], %1;" :: "l"(&g_ctr), "r"(1u) : "memory");
                    unsigned v;
                    do {
                        asm volatile("ld.acquire.gpu.u32 %0, [%1];" : "=r"(v) : "l"(&g_ctr) : "memory");
                    } while (v < target);
                }
            }
        }
        __syncthreads();   // B4: all blocks' h(t) globally visible
    }
}

// ---------------- launcher ----------------
extern "C" void kernel_launch(void* const* d_in, const int* in_sizes, int n_in,
                              void* d_out, int out_size) {
    const float* x    = (const float*)d_in[0];
    const float* Wx   = (const float*)d_in[1];
    const float* Wh   = (const float*)d_in[2];
    const float* bias = (const float*)d_in[3];
    float* out = (float*)d_out;

    cudaFuncSetAttribute(gru_scan, cudaFuncAttributeMaxDynamicSharedMemorySize, SMEM_SCAN);

    reset_k<<<1, 256>>>();
    conv_x<<<4096, 256>>>(x);
    {
        int n = N_DIM * G_DIM;
        conv_wxt<<<(n + 255) / 256, 256>>>(Wx);
    }
    {
        int n = NBLK * NWARP * NGATE * KFRAG * 32 * 4;
        pack_wh<<<(n + 255) / 256, 256>>>(Wh);
    }
    gemm_gx<<<dim3(G_DIM / 128, T_SEQ / 128), 256>>>(bias);
    gru_scan<<<NBLK, NTHR, SMEM_SCAN>>>(out);
}

// round 11
// speedup vs baseline: 5.4855x; 1.0613x over previous
#include <cuda_runtime.h>
#include <cuda_fp16.h>
#include <cstdint>

#define N_DIM  2048
#define T_SEQ  8192
#define G_DIM  6144
#define NBLK   128     // persistent blocks (1 per SM, all resident)
#define NTHR   512
#define NWARP  16
#define PB     16      // output elements per block
#define NGATE  3       // z, r, n — each gate = one 16-col A-fragment group
#define KFRAG  8       // k-fragments of 16 per warp (128 k per warp)

// ---- scratch (device globals: allocation-free rule) ----
__device__ __half        g_x16[(size_t)T_SEQ * N_DIM];          // 32 MB
__device__ __half        g_WxT16[(size_t)G_DIM * N_DIM];        // 25 MB (transposed: [n][k])
__device__ float         g_gx[(size_t)T_SEQ * G_DIM];           // 192 MB
__device__ unsigned int  g_whpack[NBLK * NWARP * NGATE * KFRAG * 32 * 4]; // 25 MB packed A-frags
__device__ unsigned long long g_hpost[2][NBLK][8];              // 8B packets: {2×fp16, tag}

// ---------------- reset ----------------
__global__ void reset_k() {
    int t = threadIdx.x;
    for (int i = t; i < 2 * NBLK * 8; i += blockDim.x)
        ((unsigned long long*)g_hpost)[i] = 0ull;   // tag=0 == valid zero h(-1) for step 0
}

// ---------------- convert x -> fp16 ----------------
__global__ void conv_x(const float* __restrict__ x) {
    const float2* x2 = (const float2*)x;
    __half2* o = (__half2*)g_x16;
    size_t n = (size_t)T_SEQ * N_DIM / 2;
    for (size_t i = blockIdx.x * (size_t)blockDim.x + threadIdx.x; i < n;
         i += (size_t)gridDim.x * blockDim.x)
        o[i] = __float22half2_rn(x2[i]);
}

// ------------- convert+transpose Wx -> WxT fp16 [n][k] -------------
__global__ void conv_wxt(const float* __restrict__ Wx) {
    size_t idx = blockIdx.x * (size_t)blockDim.x + threadIdx.x; // over K*G
    if (idx >= (size_t)N_DIM * G_DIM) return;
    int k = (int)(idx / G_DIM);
    int j = (int)(idx % G_DIM);
    g_WxT16[(size_t)j * N_DIM + k] = __float2half(Wx[idx]);
}

// ------------- pack Wh into per-block mma A fragments (fp16, weights-as-A) -------------
// idx = ((((b*16 + w)*3 + g)*8 + kf)*32 + l)*4 + r
__global__ void pack_wh(const float* __restrict__ Wh) {
    int idx = blockIdx.x * blockDim.x + threadIdx.x;
    if (idx >= NBLK * NWARP * NGATE * KFRAG * 32 * 4) return;
    int r    = idx & 3;
    int l    = (idx >> 2) & 31;
    int kf   = (idx >> 7) & 7;
    int rest = idx >> 10;          // (b*16 + w)*3 + g
    int g    = rest % 3;
    int bw   = rest / 3;
    int w    = bw & 15;
    int b    = bw >> 4;
    int tid  = l & 3, gid = l >> 2;
    int j    = g * N_DIM + b * PB + gid + ((r & 1) ? 8 : 0);   // global Wh column
    int k0   = w * 128 + kf * 16 + ((r & 2) ? 8 : 0) + 2 * tid; // global k
    __half2 h;
    h.x = __float2half(Wh[(size_t)k0 * G_DIM + j]);
    h.y = __float2half(Wh[(size_t)(k0 + 1) * G_DIM + j]);
    g_whpack[idx] = *(unsigned int*)&h;
}

// ---------------- gx = x @ Wx + b  (fp16 mma, fp32 accum) ----------------
__global__ void __launch_bounds__(256) gemm_gx(const float* __restrict__ bias) {
    __shared__ __half As[128 * 40];
    __shared__ __half Bs[128 * 40];
    const int m0 = blockIdx.y * 128, n0 = blockIdx.x * 128;
    const int t = threadIdx.x, w = t >> 5, l = t & 31, tid = l & 3, gid = l >> 2;
    const int wm = w & 3, wn = w >> 2;
    float acc[2][8][4];
#pragma unroll
    for (int mt = 0; mt < 2; ++mt)
#pragma unroll
        for (int nt = 0; nt < 8; ++nt)
#pragma unroll
            for (int q = 0; q < 4; ++q) acc[mt][nt][q] = 0.f;

    for (int kt = 0; kt < N_DIM; kt += 32) {
        {
            int r = t >> 2, c = (t & 3) * 8;
            *(uint4*)(As + r * 40 + c)        = *(const uint4*)(g_x16  + (size_t)(m0 + r)      * N_DIM + kt + c);
            *(uint4*)(As + (r + 64) * 40 + c) = *(const uint4*)(g_x16  + (size_t)(m0 + r + 64) * N_DIM + kt + c);
            *(uint4*)(Bs + r * 40 + c)        = *(const uint4*)(g_WxT16 + (size_t)(n0 + r)      * N_DIM + kt + c);
            *(uint4*)(Bs + (r + 64) * 40 + c) = *(const uint4*)(g_WxT16 + (size_t)(n0 + r + 64) * N_DIM + kt + c);
        }
        __syncthreads();
#pragma unroll
        for (int s = 0; s < 2; ++s) {
            const int ko = s * 16;
            unsigned a[2][4];
#pragma unroll
            for (int mt = 0; mt < 2; ++mt) {
                int rb = wm * 32 + mt * 16;
                a[mt][0] = *(const unsigned*)(As + (rb + gid)     * 40 + ko + 2 * tid);
                a[mt][1] = *(const unsigned*)(As + (rb + gid + 8) * 40 + ko + 2 * tid);
                a[mt][2] = *(const unsigned*)(As + (rb + gid)     * 40 + ko + 2 * tid + 8);
                a[mt][3] = *(const unsigned*)(As + (rb + gid + 8) * 40 + ko + 2 * tid + 8);
            }
#pragma unroll
            for (int nt = 0; nt < 8; ++nt) {
                int cb = wn * 64 + nt * 8 + gid;
                unsigned b0 = *(const unsigned*)(Bs + cb * 40 + ko + 2 * tid);
                unsigned b1 = *(const unsigned*)(Bs + cb * 40 + ko + 2 * tid + 8);
#pragma unroll
                for (int mt = 0; mt < 2; ++mt) {
                    asm volatile(
                        "mma.sync.aligned.m16n8k16.row.col.f32.f16.f16.f32 "
                        "{%0,%1,%2,%3},{%4,%5,%6,%7},{%8,%9},{%0,%1,%2,%3};"
                        : "+f"(acc[mt][nt][0]), "+f"(acc[mt][nt][1]),
                          "+f"(acc[mt][nt][2]), "+f"(acc[mt][nt][3])
                        : "r"(a[mt][0]), "r"(a[mt][1]), "r"(a[mt][2]), "r"(a[mt][3]),
                          "r"(b0), "r"(b1));
                }
            }
        }
        __syncthreads();
    }
#pragma unroll
    for (int mt = 0; mt < 2; ++mt)
#pragma unroll
        for (int nt = 0; nt < 8; ++nt) {
            int row = m0 + wm * 32 + mt * 16 + gid;
            int col = n0 + wn * 64 + nt * 8 + 2 * tid;
            float b0v = __ldg(bias + col), b1v = __ldg(bias + col + 1);
            g_gx[(size_t)row * G_DIM + col]           = acc[mt][nt][0] + b0v;
            g_gx[(size_t)row * G_DIM + col + 1]       = acc[mt][nt][1] + b1v;
            g_gx[(size_t)(row + 8) * G_DIM + col]     = acc[mt][nt][2] + b0v;
            g_gx[(size_t)(row + 8) * G_DIM + col + 1] = acc[mt][nt][3] + b1v;
        }
}

// ---------------- persistent GRU scan (8B-atomic tagged dataflow) ----------------
// dynamic smem layout (bytes):
//   [0,4096)      h16s broadcast (1024 u32; warp-private 256B slices)
//   [4096,10240)  red[2][16][48] f32 (parity double-buffered)
#define SMEM_SCAN 10240

__global__ void __launch_bounds__(NTHR, 1) gru_scan(float* __restrict__ out) {
    extern __shared__ unsigned char smem[];
    unsigned int*   h16s = (unsigned int*)smem;
    float*          red  = (float*)(smem + 4096);

    const int b  = blockIdx.x;
    const int t0 = threadIdx.x;
    const int w  = t0 >> 5, l = t0 & 31, tid = l & 3, gid = l >> 2;
    const int i0 = b * PB;

    const unsigned* base = g_whpack + (size_t)b * 49152;

    // ---- ALL 8 kf A-fragments into registers (persistent, 96 regs) ----
    unsigned breg[NGATE][KFRAG][4];
#pragma unroll
    for (int g = 0; g < NGATE; ++g)
#pragma unroll
        for (int kf = 0; kf < KFRAG; ++kf) {
            const uint4 v = *(const uint4*)(base + (size_t)(((w * NGATE + g) * KFRAG + kf) * 32 + l) * 4);
            breg[g][kf][0] = v.x; breg[g][kf][1] = v.y;
            breg[g][kf][2] = v.z; breg[g][kf][3] = v.w;
        }
    __syncthreads();

    // prime the gx prefetch for t=0
    if (w == 0 && l < 3) {
        const float* p = g_gx + (size_t)l * N_DIM + i0;
        asm volatile("prefetch.global.L1 [%0];" :: "l"(p));
    }

    // consumer packet mapping: warp w owns 64 packets q=0..63 (producer w*8 + q/8, word q%8),
    // dest h16s[w*64 + q]. Lane l handles q0=l and q1=l+32.
    const unsigned long long* src0 = &g_hpost[0][w * 8 + (l >> 3)][l & 7];
    const unsigned long long* src1 = &g_hpost[0][w * 8 + ((l + 32) >> 3)][(l + 32) & 7];
    const size_t bufstride = (size_t)NBLK * 8;   // u64s per parity buffer

    float hprev = 0.f;   // h state, warp 0 lanes 0..15

    for (int t = 0; t < T_SEQ; ++t) {
        // ---- prefetch NEXT step's gx lines ----
        if (w == 0 && l < 3 && t + 1 < T_SEQ) {
            const float* p = g_gx + (size_t)(t + 1) * G_DIM + (size_t)l * N_DIM + i0;
            asm volatile("prefetch.global.L1 [%0];" :: "l"(p));
        }
        // ---- gx load for THIS step ----
        float xa = 0.f, xb = 0.f;
        if (w == 0) {
            const float* gxr = g_gx + (size_t)t * G_DIM + i0;
            if (l < 16) { xa = __ldg(gxr + l); xb = __ldg(gxr + 2 * N_DIM + l); }
            else        { xa = __ldg(gxr + N_DIM + l - 16); }
        }

        // ---- tagged 8B-atomic h acquire: poll IS the data load ----
        {
            const unsigned long long* s0 = src0 + (t & 1) * bufstride;
            const unsigned long long* s1 = src1 + (t & 1) * bufstride;
            unsigned long long v;
            int got0 = 0, got1 = 0;
            do {
                if (!got0) {
                    asm volatile("ld.global.cg.b64 %0, [%1];" : "=l"(v) : "l"(s0) : "memory");
                    if ((unsigned)(v >> 32) == (unsigned)t) {
                        h16s[w * 64 + l] = (unsigned)v;
                        got0 = 1;
                    }
                }
                if (!got1) {
                    asm volatile("ld.global.cg.b64 %0, [%1];" : "=l"(v) : "l"(s1) : "memory");
                    if ((unsigned)(v >> 32) == (unsigned)t) {
                        h16s[w * 64 + 32 + l] = (unsigned)v;
                        got1 = 1;
                    }
                }
            } while (!(got0 & got1));
        }
        __syncwarp();

        // ---- mma: 3 gates x 8 kfrags; A = weights (regs), B = h replicated ----
        float acc[NGATE][4];
#pragma unroll
        for (int g = 0; g < NGATE; ++g)
#pragma unroll
            for (int q = 0; q < 4; ++q) acc[g][q] = 0.f;

#pragma unroll
        for (int kf = 0; kf < KFRAG; ++kf) {
            unsigned b0 = h16s[w * 64 + kf * 8 + tid];
            unsigned b1 = h16s[w * 64 + kf * 8 + 4 + tid];
#pragma unroll
            for (int g = 0; g < NGATE; ++g) {
                asm volatile(
                    "mma.sync.aligned.m16n8k16.row.col.f32.f16.f16.f32 "
                    "{%0,%1,%2,%3},{%4,%5,%6,%7},{%8,%9},{%0,%1,%2,%3};"
                    : "+f"(acc[g][0]), "+f"(acc[g][1]), "+f"(acc[g][2]), "+f"(acc[g][3])
                    : "r"(breg[g][kf][0]), "r"(breg[g][kf][1]),
                      "r"(breg[g][kf][2]), "r"(breg[g][kf][3]),
                      "r"(b0), "r"(b1));
            }
        }
        // ---- partials (parity double-buffered) ----
        float* redp = red + (t & 1) * 768;
        if (tid == 0) {
#pragma unroll
            for (int g = 0; g < NGATE; ++g) {
                redp[w * 48 + g * 16 + gid]     = acc[g][0];
                redp[w * 48 + g * 16 + gid + 8] = acc[g][2];
            }
        }
        __syncthreads();   // B2: the only block barrier; warps 1-15 stream into t+1 poll after it

        // ---- reduce + activation + register-packed publish (warp 0 only) ----
        if (w == 0) {
            float sa = 0.f, sb = 0.f;
#pragma unroll
            for (int ww = 0; ww < NWARP; ++ww) {
                sa += redp[ww * 48 + l];                       // l<16: z, l>=16: r
                sb += redp[ww * 48 + 32 + (l & 15)];           // n (used by lanes <16)
            }
            float sig = __fdividef(1.f, 1.f + __expf(-(xa + sa)));  // low: z, high: r
            float r   = __shfl_sync(0xffffffffu, sig, (l + 16) & 31);
            float ci  = xb + r * sb;
            ci = fminf(fmaxf(ci, -15.f), 15.f);
            float e2  = __expf(2.f * ci);
            float cand = __fdividef(e2 - 1.f, e2 + 1.f);
            float hn = fmaf(sig, cand - hprev, hprev);        // valid in lanes 0..15
            if (l < 16) {
                hprev = hn;
                out[(size_t)t * N_DIM + i0 + l] = hn;
            }
            // pack h into u32 words in registers via shfl; lane j<8 holds word j
            unsigned us = (unsigned)__half_as_ushort(__float2half(hn));
            unsigned lo = __shfl_sync(0xffffffffu, us, (2 * l) & 31);
            unsigned hi = __shfl_sync(0xffffffffu, us, (2 * l + 1) & 31);
            unsigned wreg = (hi << 16) | (lo & 0xffffu);
            if (l < 8) {
                unsigned long long pkt = (unsigned long long)wreg
                                       | ((unsigned long long)(unsigned)(t + 1) << 32);
                unsigned long long* dst = &g_hpost[(t + 1) & 1][b][l];
                asm volatile("st.global.cg.b64 [%0], %1;" :: "l"(dst), "l"(pkt) : "memory");
            }
        }
    }
}

// ---------------- launcher ----------------
extern "C" void kernel_launch(void* const* d_in, const int* in_sizes, int n_in,
                              void* d_out, int out_size) {
    const float* x    = (const float*)d_in[0];
    const float* Wx   = (const float*)d_in[1];
    const float* Wh   = (const float*)d_in[2];
    const float* bias = (const float*)d_in[3];
    float* out = (float*)d_out;

    cudaFuncSetAttribute(gru_scan, cudaFuncAttributeMaxDynamicSharedMemorySize, SMEM_SCAN);

    reset_k<<<1, 1024>>>();
    conv_x<<<4096, 256>>>(x);
    {
        int n = N_DIM * G_DIM;
        conv_wxt<<<(n + 255) / 256, 256>>>(Wx);
    }
    {
        int n = NBLK * NWARP * NGATE * KFRAG * 32 * 4;
        pack_wh<<<(n + 255) / 256, 256>>>(Wh);
    }
    gemm_gx<<<dim3(G_DIM / 128, T_SEQ / 128), 256>>>(bias);
    gru_scan<<<NBLK, NTHR, SMEM_SCAN>>>(out);
}

// round 12
// speedup vs baseline: 9.2658x; 1.6891x over previous
#include <cuda_runtime.h>
#include <cuda_fp16.h>
#include <cstdint>

#define N_DIM  2048
#define T_SEQ  8192
#define G_DIM  6144
#define NBLK   128     // persistent blocks (1 per SM, all resident)
#define NTHR   512
#define NWARP  16
#define PB     16      // output elements per block
#define NGATE  3       // z, r, n — each gate = one 16-col A-fragment group
#define KFRAG  8       // k-fragments of 16 per warp (128 k per warp)

// ---- scratch (device globals: allocation-free rule) ----
__device__ __half        g_x16[(size_t)T_SEQ * N_DIM];          // 32 MB
__device__ __half        g_WxT16[(size_t)G_DIM * N_DIM];        // 25 MB (transposed: [n][k])
__device__ float         g_gx[(size_t)T_SEQ * G_DIM];           // 192 MB
__device__ unsigned int  g_whpack[NBLK * NWARP * NGATE * KFRAG * 32 * 4]; // 25 MB packed A-frags
__device__ unsigned long long g_hpost[2][NBLK][8];              // 8B packets: {2×fp16, tag}

// ---------------- fused prep: reset + conv_x + conv_wxt + pack_wh ----------------
__global__ void prep(const float* __restrict__ x,
                     const float* __restrict__ Wx,
                     const float* __restrict__ Wh) {
    const size_t tg = blockIdx.x * (size_t)blockDim.x + threadIdx.x;
    const size_t nt = (size_t)gridDim.x * blockDim.x;

    // job 0: reset h packets (tag=0 == valid zero h(-1) for step 0)
    for (size_t i = tg; i < 2 * NBLK * 8; i += nt)
        ((unsigned long long*)g_hpost)[i] = 0ull;

    // job 1: x -> fp16
    {
        const float2* x2 = (const float2*)x;
        __half2* o = (__half2*)g_x16;
        const size_t n = (size_t)T_SEQ * N_DIM / 2;
        for (size_t i = tg; i < n; i += nt)
            o[i] = __float22half2_rn(x2[i]);
    }
    // job 2: Wx -> WxT fp16 [n][k]
    {
        const size_t n = (size_t)N_DIM * G_DIM;
        for (size_t i = tg; i < n; i += nt) {
            int k = (int)(i / G_DIM);
            int j = (int)(i % G_DIM);
            g_WxT16[(size_t)j * N_DIM + k] = __float2half(Wx[i]);
        }
    }
    // job 3: Wh -> packed A-fragments
    {
        const size_t n = (size_t)NBLK * NWARP * NGATE * KFRAG * 32 * 4;
        for (size_t ii = tg; ii < n; ii += nt) {
            int idx  = (int)ii;
            int r    = idx & 3;
            int l    = (idx >> 2) & 31;
            int kf   = (idx >> 7) & 7;
            int rest = idx >> 10;          // (b*16 + w)*3 + g
            int g    = rest % 3;
            int bw   = rest / 3;
            int w    = bw & 15;
            int b    = bw >> 4;
            int tid  = l & 3, gid = l >> 2;
            int j    = g * N_DIM + b * PB + gid + ((r & 1) ? 8 : 0);
            int k0   = w * 128 + kf * 16 + ((r & 2) ? 8 : 0) + 2 * tid;
            __half2 h;
            h.x = __float2half(Wh[(size_t)k0 * G_DIM + j]);
            h.y = __float2half(Wh[(size_t)(k0 + 1) * G_DIM + j]);
            g_whpack[idx] = *(unsigned int*)&h;
        }
    }
}

// ---------------- gx = x @ Wx + b  (fp16 mma, fp32 accum) ----------------
__global__ void __launch_bounds__(256) gemm_gx(const float* __restrict__ bias) {
    __shared__ __half As[128 * 40];
    __shared__ __half Bs[128 * 40];
    const int m0 = blockIdx.y * 128, n0 = blockIdx.x * 128;
    const int t = threadIdx.x, w = t >> 5, l = t & 31, tid = l & 3, gid = l >> 2;
    const int wm = w & 3, wn = w >> 2;
    float acc[2][8][4];
#pragma unroll
    for (int mt = 0; mt < 2; ++mt)
#pragma unroll
        for (int nt = 0; nt < 8; ++nt)
#pragma unroll
            for (int q = 0; q < 4; ++q) acc[mt][nt][q] = 0.f;

    for (int kt = 0; kt < N_DIM; kt += 32) {
        {
            int r = t >> 2, c = (t & 3) * 8;
            *(uint4*)(As + r * 40 + c)        = *(const uint4*)(g_x16  + (size_t)(m0 + r)      * N_DIM + kt + c);
            *(uint4*)(As + (r + 64) * 40 + c) = *(const uint4*)(g_x16  + (size_t)(m0 + r + 64) * N_DIM + kt + c);
            *(uint4*)(Bs + r * 40 + c)        = *(const uint4*)(g_WxT16 + (size_t)(n0 + r)      * N_DIM + kt + c);
            *(uint4*)(Bs + (r + 64) * 40 + c) = *(const uint4*)(g_WxT16 + (size_t)(n0 + r + 64) * N_DIM + kt + c);
        }
        __syncthreads();
#pragma unroll
        for (int s = 0; s < 2; ++s) {
            const int ko = s * 16;
            unsigned a[2][4];
#pragma unroll
            for (int mt = 0; mt < 2; ++mt) {
                int rb = wm * 32 + mt * 16;
                a[mt][0] = *(const unsigned*)(As + (rb + gid)     * 40 + ko + 2 * tid);
                a[mt][1] = *(const unsigned*)(As + (rb + gid + 8) * 40 + ko + 2 * tid);
                a[mt][2] = *(const unsigned*)(As + (rb + gid)     * 40 + ko + 2 * tid + 8);
                a[mt][3] = *(const unsigned*)(As + (rb + gid + 8) * 40 + ko + 2 * tid + 8);
            }
#pragma unroll
            for (int nt = 0; nt < 8; ++nt) {
                int cb = wn * 64 + nt * 8 + gid;
                unsigned b0 = *(const unsigned*)(Bs + cb * 40 + ko + 2 * tid);
                unsigned b1 = *(const unsigned*)(Bs + cb * 40 + ko + 2 * tid + 8);
#pragma unroll
                for (int mt = 0; mt < 2; ++mt) {
                    asm volatile(
                        "mma.sync.aligned.m16n8k16.row.col.f32.f16.f16.f32 "
                        "{%0,%1,%2,%3},{%4,%5,%6,%7},{%8,%9},{%0,%1,%2,%3};"
                        : "+f"(acc[mt][nt][0]), "+f"(acc[mt][nt][1]),
                          "+f"(acc[mt][nt][2]), "+f"(acc[mt][nt][3])
                        : "r"(a[mt][0]), "r"(a[mt][1]), "r"(a[mt][2]), "r"(a[mt][3]),
                          "r"(b0), "r"(b1));
                }
            }
        }
        __syncthreads();
    }
#pragma unroll
    for (int mt = 0; mt < 2; ++mt)
#pragma unroll
        for (int nt = 0; nt < 8; ++nt) {
            int row = m0 + wm * 32 + mt * 16 + gid;
            int col = n0 + wn * 64 + nt * 8 + 2 * tid;
            float b0v = __ldg(bias + col), b1v = __ldg(bias + col + 1);
            g_gx[(size_t)row * G_DIM + col]           = acc[mt][nt][0] + b0v;
            g_gx[(size_t)row * G_DIM + col + 1]       = acc[mt][nt][1] + b1v;
            g_gx[(size_t)(row + 8) * G_DIM + col]     = acc[mt][nt][2] + b0v;
            g_gx[(size_t)(row + 8) * G_DIM + col + 1] = acc[mt][nt][3] + b1v;
        }
}

// ---------------- persistent GRU scan (8B-atomic tagged dataflow; register B-path) ----------------
// dynamic smem layout (bytes):
//   [0,6144)  red[2][16][48] f32 (parity double-buffered)
#define SMEM_SCAN 6144

__global__ void __launch_bounds__(NTHR, 1) gru_scan(float* __restrict__ out) {
    extern __shared__ unsigned char smem[];
    float* red = (float*)smem;

    const int b  = blockIdx.x;
    const int t0 = threadIdx.x;
    const int w  = t0 >> 5, l = t0 & 31, tid = l & 3, gid = l >> 2;
    const int i0 = b * PB;

    const unsigned* base = g_whpack + (size_t)b * 49152;

    // ---- ALL 8 kf A-fragments into registers (persistent, 96 regs) ----
    unsigned breg[NGATE][KFRAG][4];
#pragma unroll
    for (int g = 0; g < NGATE; ++g)
#pragma unroll
        for (int kf = 0; kf < KFRAG; ++kf) {
            const uint4 v = *(const uint4*)(base + (size_t)(((w * NGATE + g) * KFRAG + kf) * 32 + l) * 4);
            breg[g][kf][0] = v.x; breg[g][kf][1] = v.y;
            breg[g][kf][2] = v.z; breg[g][kf][3] = v.w;
        }
    __syncthreads();

    // prime the gx prefetch for t=0
    if (w == 0 && l < 3) {
        const float* p = g_gx + (size_t)l * N_DIM + i0;
        asm volatile("prefetch.global.L1 [%0];" :: "l"(p));
    }

    // consumer packet mapping: warp w owns region words q=0..63 (producer w*8 + q/8, word q%8).
    // Lane l polls q0=l and q1=l+32 into registers p0/p1.
    const unsigned long long* src0 = &g_hpost[0][w * 8 + (l >> 3)][l & 7];
    const unsigned long long* src1 = &g_hpost[0][w * 8 + ((l + 32) >> 3)][(l + 32) & 7];
    const size_t bufstride = (size_t)NBLK * 8;   // u64s per parity buffer

    float hprev = 0.f;   // h state, warp 0 lanes 0..15

    for (int t = 0; t < T_SEQ; ++t) {
        // ---- prefetch NEXT step's gx lines ----
        if (w == 0 && l < 3 && t + 1 < T_SEQ) {
            const float* p = g_gx + (size_t)(t + 1) * G_DIM + (size_t)l * N_DIM + i0;
            asm volatile("prefetch.global.L1 [%0];" :: "l"(p));
        }
        // ---- gx load for THIS step ----
        float xa = 0.f, xb = 0.f;
        if (w == 0) {
            const float* gxr = g_gx + (size_t)t * G_DIM + i0;
            if (l < 16) { xa = __ldg(gxr + l); xb = __ldg(gxr + 2 * N_DIM + l); }
            else        { xa = __ldg(gxr + N_DIM + l - 16); }
        }

        // ---- tagged 8B-atomic h acquire into registers ----
        unsigned p0, p1;
        {
            const unsigned long long* s0 = src0 + (t & 1) * bufstride;
            const unsigned long long* s1 = src1 + (t & 1) * bufstride;
            unsigned long long v;
            int got0 = 0, got1 = 0;
            do {
                if (!got0) {
                    asm volatile("ld.global.cg.b64 %0, [%1];" : "=l"(v) : "l"(s0) : "memory");
                    if ((unsigned)(v >> 32) == (unsigned)t) { p0 = (unsigned)v; got0 = 1; }
                }
                if (!got1) {
                    asm volatile("ld.global.cg.b64 %0, [%1];" : "=l"(v) : "l"(s1) : "memory");
                    if ((unsigned)(v >> 32) == (unsigned)t) { p1 = (unsigned)v; got1 = 1; }
                }
            } while (!(got0 & got1));
        }

        // ---- mma: B operands distributed via shfl (no smem staging) ----
        float acc[NGATE][4];
#pragma unroll
        for (int g = 0; g < NGATE; ++g)
#pragma unroll
            for (int q = 0; q < 4; ++q) acc[g][q] = 0.f;

#pragma unroll
        for (int kf = 0; kf < KFRAG; ++kf) {
            unsigned srcreg = (kf < 4) ? p0 : p1;
            unsigned b0 = __shfl_sync(0xffffffffu, srcreg, (kf * 8 + tid) & 31);
            unsigned b1 = __shfl_sync(0xffffffffu, srcreg, (kf * 8 + 4 + tid) & 31);
#pragma unroll
            for (int g = 0; g < NGATE; ++g) {
                asm volatile(
                    "mma.sync.aligned.m16n8k16.row.col.f32.f16.f16.f32 "
                    "{%0,%1,%2,%3},{%4,%5,%6,%7},{%8,%9},{%0,%1,%2,%3};"
                    : "+f"(acc[g][0]), "+f"(acc[g][1]), "+f"(acc[g][2]), "+f"(acc[g][3])
                    : "r"(breg[g][kf][0]), "r"(breg[g][kf][1]),
                      "r"(breg[g][kf][2]), "r"(breg[g][kf][3]),
                      "r"(b0), "r"(b1));
            }
        }
        // ---- partials (parity double-buffered) ----
        float* redp = red + (t & 1) * 768;
        if (tid == 0) {
#pragma unroll
            for (int g = 0; g < NGATE; ++g) {
                redp[w * 48 + g * 16 + gid]     = acc[g][0];
                redp[w * 48 + g * 16 + gid + 8] = acc[g][2];
            }
        }
        __syncthreads();   // B2: the only block barrier

        // ---- reduce + activation + register-packed publish (warp 0 only) ----
        if (w == 0) {
            float sa = 0.f, sb = 0.f;
#pragma unroll
            for (int ww = 0; ww < NWARP; ++ww) {
                sa += redp[ww * 48 + l];                       // l<16: z, l>=16: r
                sb += redp[ww * 48 + 32 + (l & 15)];           // n (used by lanes <16)
            }
            float sig = __fdividef(1.f, 1.f + __expf(-(xa + sa)));  // low: z, high: r
            float r   = __shfl_sync(0xffffffffu, sig, (l + 16) & 31);
            float ci  = xb + r * sb;
            ci = fminf(fmaxf(ci, -15.f), 15.f);
            float e2  = __expf(2.f * ci);
            float cand = __fdividef(e2 - 1.f, e2 + 1.f);
            float hn = fmaf(sig, cand - hprev, hprev);        // valid in lanes 0..15
            if (l < 16) {
                hprev = hn;
                out[(size_t)t * N_DIM + i0 + l] = hn;
            }
            // pack h into u32 words in registers via shfl; lane j<8 holds word j
            unsigned us = (unsigned)__half_as_ushort(__float2half(hn));
            unsigned lo = __shfl_sync(0xffffffffu, us, (2 * l) & 31);
            unsigned hi = __shfl_sync(0xffffffffu, us, (2 * l + 1) & 31);
            unsigned wreg = (hi << 16) | (lo & 0xffffu);
            if (l < 8) {
                unsigned long long pkt = (unsigned long long)wreg
                                       | ((unsigned long long)(unsigned)(t + 1) << 32);
                unsigned long long* dst = &g_hpost[(t + 1) & 1][b][l];
                asm volatile("st.global.cg.b64 [%0], %1;" :: "l"(dst), "l"(pkt) : "memory");
            }
        }
    }
}

// ---------------- launcher ----------------
extern "C" void kernel_launch(void* const* d_in, const int* in_sizes, int n_in,
                              void* d_out, int out_size) {
    const float* x    = (const float*)d_in[0];
    const float* Wx   = (const float*)d_in[1];
    const float* Wh   = (const float*)d_in[2];
    const float* bias = (const float*)d_in[3];
    float* out = (float*)d_out;

    cudaFuncSetAttribute(gru_scan, cudaFuncAttributeMaxDynamicSharedMemorySize, SMEM_SCAN);

    prep<<<4096, 256>>>(x, Wx, Wh);
    gemm_gx<<<dim3(G_DIM / 128, T_SEQ / 128), 256>>>(bias);
    gru_scan<<<NBLK, NTHR, SMEM_SCAN>>>(out);
}

// round 13
// speedup vs baseline: 9.4135x; 1.0159x over previous
#include <cuda_runtime.h>
#include <cuda_fp16.h>
#include <cstdint>

#define N_DIM  2048
#define T_SEQ  8192
#define G_DIM  6144
#define NBLK   128     // persistent blocks (1 per SM, all resident)
#define NTHR   512
#define NWARP  16
#define PB     16      // output elements per block
#define NGATE  3       // z, r, n — each gate = one 16-col A-fragment group
#define KFRAG  8       // k-fragments of 16 per warp (128 k per warp)

// ---- scratch (device globals: allocation-free rule) ----
__device__ __half        g_x16[(size_t)T_SEQ * N_DIM];          // 32 MB
__device__ __half        g_WxT16[(size_t)G_DIM * N_DIM];        // 25 MB (transposed: [n][k])
__device__ float         g_gx[(size_t)T_SEQ * G_DIM];           // 192 MB
__device__ unsigned int  g_whpack[NBLK * NWARP * NGATE * KFRAG * 32 * 4]; // 25 MB packed A-frags
__device__ unsigned long long g_hpost[2][NBLK][8];              // 8B packets: {2×fp16, tag}

// ---------------- fused prep: reset + conv_x + tiled WxT transpose + pack_wh ----------------
__global__ void prep(const float* __restrict__ x,
                     const float* __restrict__ Wx,
                     const float* __restrict__ Wh) {
    __shared__ __half tile[32][72];   // 32 k-rows x 64 j-cols, padded
    const size_t tg = blockIdx.x * (size_t)blockDim.x + threadIdx.x;
    const size_t nt = (size_t)gridDim.x * blockDim.x;
    const int    tl = threadIdx.x;

    // job 0: reset h packets (tag=0 == valid zero h(-1) for step 0)
    for (size_t i = tg; i < 2 * NBLK * 8; i += nt)
        ((unsigned long long*)g_hpost)[i] = 0ull;

    // job 1: x -> fp16
    {
        const float2* x2 = (const float2*)x;
        __half2* o = (__half2*)g_x16;
        const size_t n = (size_t)T_SEQ * N_DIM / 2;
        for (size_t i = tg; i < n; i += nt)
            o[i] = __float22half2_rn(x2[i]);
    }
    // job 3: Wh -> packed A-fragments
    {
        const size_t n = (size_t)NBLK * NWARP * NGATE * KFRAG * 32 * 4;
        for (size_t ii = tg; ii < n; ii += nt) {
            int idx  = (int)ii;
            int r    = idx & 3;
            int l    = (idx >> 2) & 31;
            int kf   = (idx >> 7) & 7;
            int rest = idx >> 10;          // (b*16 + w)*3 + g
            int g    = rest % 3;
            int bw   = rest / 3;
            int w    = bw & 15;
            int b    = bw >> 4;
            int tid  = l & 3, gid = l >> 2;
            int j    = g * N_DIM + b * PB + gid + ((r & 1) ? 8 : 0);
            int k0   = w * 128 + kf * 16 + ((r & 2) ? 8 : 0) + 2 * tid;
            __half2 h;
            h.x = __float2half(Wh[(size_t)k0 * G_DIM + j]);
            h.y = __float2half(Wh[(size_t)(k0 + 1) * G_DIM + j]);
            g_whpack[idx] = *(unsigned int*)&h;
        }
    }
    // job 2 (last; block-uniform): Wx -> WxT fp16 [n][k], tiled smem transpose
    {
        const int ntile = (N_DIM / 32) * (G_DIM / 64);   // 64 * 96 = 6144
        for (int tix = blockIdx.x; tix < ntile; tix += gridDim.x) {
            int tk = tix & 63, tj = tix >> 6;
            int k0 = tk * 32, j0 = tj * 64;
            __syncthreads();
#pragma unroll
            for (int e = 0; e < 8; ++e) {
                int idx = tl + e * 256;         // 0..2047
                int kk = idx >> 6, jj = idx & 63;
                tile[kk][jj] = __float2half(Wx[(size_t)(k0 + kk) * G_DIM + j0 + jj]);
            }
            __syncthreads();
#pragma unroll
            for (int e = 0; e < 8; ++e) {
                int idx = tl + e * 256;
                int jj = idx >> 5, kk = idx & 31;
                g_WxT16[(size_t)(j0 + jj) * N_DIM + k0 + kk] = tile[kk][jj];
            }
        }
    }
}

// ---------------- gx = x @ Wx + b  (fp16 mma, fp32 accum, 2-stage cp.async) ----------------
#define CP_ASYNC16(sa, gp) \
    asm volatile("cp.async.ca.shared.global [%0], [%1], 16;" :: "r"(sa), "l"(gp))
#define CP_COMMIT() asm volatile("cp.async.commit_group;" ::: "memory")

__global__ void __launch_bounds__(256) gemm_gx(const float* __restrict__ bias) {
    __shared__ __half As[2][128 * 40];
    __shared__ __half Bs[2][128 * 40];
    const int m0 = blockIdx.y * 128, n0 = blockIdx.x * 128;
    const int t = threadIdx.x, w = t >> 5, l = t & 31, tid = l & 3, gid = l >> 2;
    const int wm = w & 3, wn = w >> 2;
    const int r = t >> 2, c = (t & 3) * 8;

    float acc[2][8][4];
#pragma unroll
    for (int mt = 0; mt < 2; ++mt)
#pragma unroll
        for (int nt = 0; nt < 8; ++nt)
#pragma unroll
            for (int q = 0; q < 4; ++q) acc[mt][nt][q] = 0.f;

    auto load_stage = [&](int s, int kt) {
        unsigned a0 = (unsigned)__cvta_generic_to_shared(&As[s][r * 40 + c]);
        unsigned a1 = (unsigned)__cvta_generic_to_shared(&As[s][(r + 64) * 40 + c]);
        unsigned b0 = (unsigned)__cvta_generic_to_shared(&Bs[s][r * 40 + c]);
        unsigned b1 = (unsigned)__cvta_generic_to_shared(&Bs[s][(r + 64) * 40 + c]);
        CP_ASYNC16(a0, g_x16  + (size_t)(m0 + r)      * N_DIM + kt + c);
        CP_ASYNC16(a1, g_x16  + (size_t)(m0 + r + 64) * N_DIM + kt + c);
        CP_ASYNC16(b0, g_WxT16 + (size_t)(n0 + r)      * N_DIM + kt + c);
        CP_ASYNC16(b1, g_WxT16 + (size_t)(n0 + r + 64) * N_DIM + kt + c);
        CP_COMMIT();
    };

    load_stage(0, 0);
    const int NIT = N_DIM / 32;
    for (int i = 0; i < NIT; ++i) {
        const int s = i & 1;
        if (i + 1 < NIT) {
            load_stage(s ^ 1, (i + 1) * 32);
            asm volatile("cp.async.wait_group 1;" ::: "memory");
        } else {
            asm volatile("cp.async.wait_group 0;" ::: "memory");
        }
        __syncthreads();
#pragma unroll
        for (int sj = 0; sj < 2; ++sj) {
            const int ko = sj * 16;
            unsigned a[2][4];
#pragma unroll
            for (int mt = 0; mt < 2; ++mt) {
                int rb = wm * 32 + mt * 16;
                a[mt][0] = *(const unsigned*)(&As[s][(rb + gid)     * 40 + ko + 2 * tid]);
                a[mt][1] = *(const unsigned*)(&As[s][(rb + gid + 8) * 40 + ko + 2 * tid]);
                a[mt][2] = *(const unsigned*)(&As[s][(rb + gid)     * 40 + ko + 2 * tid + 8]);
                a[mt][3] = *(const unsigned*)(&As[s][(rb + gid + 8) * 40 + ko + 2 * tid + 8]);
            }
#pragma unroll
            for (int nt = 0; nt < 8; ++nt) {
                int cb = wn * 64 + nt * 8 + gid;
                unsigned b0 = *(const unsigned*)(&Bs[s][cb * 40 + ko + 2 * tid]);
                unsigned b1 = *(const unsigned*)(&Bs[s][cb * 40 + ko + 2 * tid + 8]);
#pragma unroll
                for (int mt = 0; mt < 2; ++mt) {
                    asm volatile(
                        "mma.sync.aligned.m16n8k16.row.col.f32.f16.f16.f32 "
                        "{%0,%1,%2,%3},{%4,%5,%6,%7},{%8,%9},{%0,%1,%2,%3};"
                        : "+f"(acc[mt][nt][0]), "+f"(acc[mt][nt][1]),
                          "+f"(acc[mt][nt][2]), "+f"(acc[mt][nt][3])
                        : "r"(a[mt][0]), "r"(a[mt][1]), "r"(a[mt][2]), "r"(a[mt][3]),
                          "r"(b0), "r"(b1));
                }
            }
        }
        __syncthreads();
    }
#pragma unroll
    for (int mt = 0; mt < 2; ++mt)
#pragma unroll
        for (int nt = 0; nt < 8; ++nt) {
            int row = m0 + wm * 32 + mt * 16 + gid;
            int col = n0 + wn * 64 + nt * 8 + 2 * tid;
            float b0v = __ldg(bias + col), b1v = __ldg(bias + col + 1);
            g_gx[(size_t)row * G_DIM + col]           = acc[mt][nt][0] + b0v;
            g_gx[(size_t)row * G_DIM + col + 1]       = acc[mt][nt][1] + b1v;
            g_gx[(size_t)(row + 8) * G_DIM + col]     = acc[mt][nt][2] + b0v;
            g_gx[(size_t)(row + 8) * G_DIM + col + 1] = acc[mt][nt][3] + b1v;
        }
}

// ---------------- persistent GRU scan (8B-atomic tagged dataflow; register B-path) ----------------
// UNCHANGED from R12 (byte-frozen local optimum)
#define SMEM_SCAN 6144

__global__ void __launch_bounds__(NTHR, 1) gru_scan(float* __restrict__ out) {
    extern __shared__ unsigned char smem[];
    float* red = (float*)smem;

    const int b  = blockIdx.x;
    const int t0 = threadIdx.x;
    const int w  = t0 >> 5, l = t0 & 31, tid = l & 3, gid = l >> 2;
    const int i0 = b * PB;

    const unsigned* base = g_whpack + (size_t)b * 49152;

    unsigned breg[NGATE][KFRAG][4];
#pragma unroll
    for (int g = 0; g < NGATE; ++g)
#pragma unroll
        for (int kf = 0; kf < KFRAG; ++kf) {
            const uint4 v = *(const uint4*)(base + (size_t)(((w * NGATE + g) * KFRAG + kf) * 32 + l) * 4);
            breg[g][kf][0] = v.x; breg[g][kf][1] = v.y;
            breg[g][kf][2] = v.z; breg[g][kf][3] = v.w;
        }
    __syncthreads();

    if (w == 0 && l < 3) {
        const float* p = g_gx + (size_t)l * N_DIM + i0;
        asm volatile("prefetch.global.L1 [%0];" :: "l"(p));
    }

    const unsigned long long* src0 = &g_hpost[0][w * 8 + (l >> 3)][l & 7];
    const unsigned long long* src1 = &g_hpost[0][w * 8 + ((l + 32) >> 3)][(l + 32) & 7];
    const size_t bufstride = (size_t)NBLK * 8;

    float hprev = 0.f;

    for (int t = 0; t < T_SEQ; ++t) {
        if (w == 0 && l < 3 && t + 1 < T_SEQ) {
            const float* p = g_gx + (size_t)(t + 1) * G_DIM + (size_t)l * N_DIM + i0;
            asm volatile("prefetch.global.L1 [%0];" :: "l"(p));
        }
        float xa = 0.f, xb = 0.f;
        if (w == 0) {
            const float* gxr = g_gx + (size_t)t * G_DIM + i0;
            if (l < 16) { xa = __ldg(gxr + l); xb = __ldg(gxr + 2 * N_DIM + l); }
            else        { xa = __ldg(gxr + N_DIM + l - 16); }
        }

        unsigned p0, p1;
        {
            const unsigned long long* s0 = src0 + (t & 1) * bufstride;
            const unsigned long long* s1 = src1 + (t & 1) * bufstride;
            unsigned long long v;
            int got0 = 0, got1 = 0;
            do {
                if (!got0) {
                    asm volatile("ld.global.cg.b64 %0, [%1];" : "=l"(v) : "l"(s0) : "memory");
                    if ((unsigned)(v >> 32) == (unsigned)t) { p0 = (unsigned)v; got0 = 1; }
                }
                if (!got1) {
                    asm volatile("ld.global.cg.b64 %0, [%1];" : "=l"(v) : "l"(s1) : "memory");
                    if ((unsigned)(v >> 32) == (unsigned)t) { p1 = (unsigned)v; got1 = 1; }
                }
            } while (!(got0 & got1));
        }

        float acc[NGATE][4];
#pragma unroll
        for (int g = 0; g < NGATE; ++g)
#pragma unroll
            for (int q = 0; q < 4; ++q) acc[g][q] = 0.f;

#pragma unroll
        for (int kf = 0; kf < KFRAG; ++kf) {
            unsigned srcreg = (kf < 4) ? p0 : p1;
            unsigned b0 = __shfl_sync(0xffffffffu, srcreg, (kf * 8 + tid) & 31);
            unsigned b1 = __shfl_sync(0xffffffffu, srcreg, (kf * 8 + 4 + tid) & 31);
#pragma unroll
            for (int g = 0; g < NGATE; ++g) {
                asm volatile(
                    "mma.sync.aligned.m16n8k16.row.col.f32.f16.f16.f32 "
                    "{%0,%1,%2,%3},{%4,%5,%6,%7},{%8,%9},{%0,%1,%2,%3};"
                    : "+f"(acc[g][0]), "+f"(acc[g][1]), "+f"(acc[g][2]), "+f"(acc[g][3])
                    : "r"(breg[g][kf][0]), "r"(breg[g][kf][1]),
                      "r"(breg[g][kf][2]), "r"(breg[g][kf][3]),
                      "r"(b0), "r"(b1));
            }
        }
        float* redp = red + (t & 1) * 768;
        if (tid == 0) {
#pragma unroll
            for (int g = 0; g < NGATE; ++g) {
                redp[w * 48 + g * 16 + gid]     = acc[g][0];
                redp[w * 48 + g * 16 + gid + 8] = acc[g][2];
            }
        }
        __syncthreads();

        if (w == 0) {
            float sa = 0.f, sb = 0.f;
#pragma unroll
            for (int ww = 0; ww < NWARP; ++ww) {
                sa += redp[ww * 48 + l];
                sb += redp[ww * 48 + 32 + (l & 15)];
            }
            float sig = __fdividef(1.f, 1.f + __expf(-(xa + sa)));
            float r   = __shfl_sync(0xffffffffu, sig, (l + 16) & 31);
            float ci  = xb + r * sb;
            ci = fminf(fmaxf(ci, -15.f), 15.f);
            float e2  = __expf(2.f * ci);
            float cand = __fdividef(e2 - 1.f, e2 + 1.f);
            float hn = fmaf(sig, cand - hprev, hprev);
            if (l < 16) {
                hprev = hn;
                out[(size_t)t * N_DIM + i0 + l] = hn;
            }
            unsigned us = (unsigned)__half_as_ushort(__float2half(hn));
            unsigned lo = __shfl_sync(0xffffffffu, us, (2 * l) & 31);
            unsigned hi = __shfl_sync(0xffffffffu, us, (2 * l + 1) & 31);
            unsigned wreg = (hi << 16) | (lo & 0xffffu);
            if (l < 8) {
                unsigned long long pkt = (unsigned long long)wreg
                                       | ((unsigned long long)(unsigned)(t + 1) << 32);
                unsigned long long* dst = &g_hpost[(t + 1) & 1][b][l];
                asm volatile("st.global.cg.b64 [%0], %1;" :: "l"(dst), "l"(pkt) : "memory");
            }
        }
    }
}

// ---------------- launcher ----------------
extern "C" void kernel_launch(void* const* d_in, const int* in_sizes, int n_in,
                              void* d_out, int out_size) {
    const float* x    = (const float*)d_in[0];
    const float* Wx   = (const float*)d_in[1];
    const float* Wh   = (const float*)d_in[2];
    const float* bias = (const float*)d_in[3];
    float* out = (float*)d_out;

    cudaFuncSetAttribute(gru_scan, cudaFuncAttributeMaxDynamicSharedMemorySize, SMEM_SCAN);

    prep<<<4096, 256>>>(x, Wx, Wh);
    gemm_gx<<<dim3(G_DIM / 128, T_SEQ / 128), 256>>>(bias);
    gru_scan<<<NBLK, NTHR, SMEM_SCAN>>>(out);
}